// round 4
// baseline (speedup 1.0000x reference)
#include <cuda_runtime.h>
#include <math.h>
#include <stdint.h>

// Problem constants
#define BATCH   64
#define HDIM    28
#define WDIM    28
#define C_      512
#define HEADS_  16
#define WS_     7
#define SHIFT_  3
#define MLPD    2048
#define HD_     32
#define W2_     49
#define NW_     16
#define HW_     784
#define MTOK    50176   // BATCH*HW
#define NWIN    1024    // BATCH*NW

// Scratch (device globals: no allocation allowed in kernel_launch)
__device__ float g_win[MTOK * C_];
__device__ float g_q[MTOK * C_];
__device__ float g_k[MTOK * C_];
__device__ float g_v[MTOK * C_];
__device__ float g_ctx[MTOK * C_];
__device__ float g_x1[MTOK * C_];
__device__ float g_h2[MTOK * C_];
__device__ float g_mid[(size_t)MTOK * MLPD];

// Map window-partition row m -> token row in the unshifted [B,H*W] layout.
__device__ __forceinline__ int map_row(int m) {
    int bb  = m / HW_;
    int rem = m - bb * HW_;
    int w   = rem / W2_;
    int t   = rem - w * W2_;
    int wh = w >> 2, ww = w & 3;
    int th = t / WS_, tw = t - th * WS_;
    int r = wh * WS_ + th + SHIFT_; if (r >= HDIM) r -= HDIM;
    int c = ww * WS_ + tw + SHIFT_; if (c >= WDIM) c -= WDIM;
    return bb * HW_ + r * WDIM + c;
}

// LayerNorm over C=512, one block per token row.
__global__ __launch_bounds__(128) void ln_kernel(
    const float* __restrict__ in, const float* __restrict__ g,
    const float* __restrict__ b, float* __restrict__ out, int gather)
{
    int m = blockIdx.x;
    int src = gather ? map_row(m) : m;
    int tid = threadIdx.x;

    float4 xv = ((const float4*)(in + (size_t)src * C_))[tid];
    float s  = xv.x + xv.y + xv.z + xv.w;
    float s2 = xv.x*xv.x + xv.y*xv.y + xv.z*xv.z + xv.w*xv.w;
    #pragma unroll
    for (int off = 16; off; off >>= 1) {
        s  += __shfl_xor_sync(0xffffffffu, s,  off);
        s2 += __shfl_xor_sync(0xffffffffu, s2, off);
    }
    __shared__ float red[8];
    int wid = tid >> 5;
    if ((tid & 31) == 0) { red[wid] = s; red[4 + wid] = s2; }
    __syncthreads();
    s  = red[0] + red[1] + red[2] + red[3];
    s2 = red[4] + red[5] + red[6] + red[7];
    float mu   = s * (1.0f / C_);
    float var  = fmaf(-mu, mu, s2 * (1.0f / C_));
    float rstd = rsqrtf(var + 1e-5f);

    float4 gv = ((const float4*)g)[tid];
    float4 bv = ((const float4*)b)[tid];
    float4 o;
    o.x = (xv.x - mu) * rstd * gv.x + bv.x;
    o.y = (xv.y - mu) * rstd * gv.y + bv.y;
    o.z = (xv.z - mu) * rstd * gv.z + bv.z;
    o.w = (xv.w - mu) * rstd * gv.w + bv.w;
    ((float4*)(out + (size_t)m * C_))[tid] = o;
}

// ---------------------------------------------------------------------------
// TF32 tensor-core GEMM with cp.async double buffering.
// C[M,N] = A[M,K] @ B[K,N] + bias, epilogue modes.
// 256 threads = 8 warps (2 x 4), block tile 128x128, BK=16, warp tile 64x32.
// fp32 operands fed to mma.tf32 directly (HW truncation).
// mode 0: plain   mode 1: exact GELU   mode 2: += res[m]
// mode 3: scatter row via map_row(m), += res[out_row]
// ---------------------------------------------------------------------------
#define BM 128
#define BN 128
#define BKT 16
#define ASTR 20   // As row stride (floats): conflict-free (20g+t covers banks)
#define BSTR 136  // Bs row stride (floats): 136 mod 32 = 8 -> 8t+g covers banks

__device__ __forceinline__ void cpa16(void* smem_dst, const void* gsrc) {
    uint32_t s = (uint32_t)__cvta_generic_to_shared(smem_dst);
    asm volatile("cp.async.cg.shared.global [%0], [%1], 16;\n" :: "r"(s), "l"(gsrc));
}

__device__ __forceinline__ void mma_tf32(float c[4], uint32_t a0, uint32_t a1,
                                         uint32_t a2, uint32_t a3,
                                         uint32_t b0, uint32_t b1) {
    asm volatile(
        "mma.sync.aligned.m16n8k8.row.col.f32.tf32.tf32.f32 "
        "{%0,%1,%2,%3}, {%4,%5,%6,%7}, {%8,%9}, {%0,%1,%2,%3};"
        : "+f"(c[0]), "+f"(c[1]), "+f"(c[2]), "+f"(c[3])
        : "r"(a0), "r"(a1), "r"(a2), "r"(a3), "r"(b0), "r"(b1));
}

__global__ __launch_bounds__(256) void tgemm_kernel(
    const float* __restrict__ A, const float* __restrict__ Bm,
    const float* __restrict__ bias, float* __restrict__ C,
    int M, int N, int K, int mode, const float* __restrict__ res)
{
    __shared__ float As[2][BM * ASTR];
    __shared__ float Bs[2][BKT * BSTR];

    const int cRow = blockIdx.y, cCol = blockIdx.x;
    const int tid  = threadIdx.x;
    const int wid  = tid >> 5;
    const int lane = tid & 31;
    const int wm   = wid >> 2;       // 0..1
    const int wn   = wid & 3;        // 0..3
    const int grp  = lane >> 2;      // 0..7
    const int tig  = lane & 3;       // 0..3

    const float* Ab = A  + (size_t)cRow * BM * K;
    const float* Bb = Bm + (size_t)cCol * BN;

    // cp.async mapping: 2 A chunks + 2 B chunks per thread per tile
    const int aRow0 = tid >> 1;              // chunk0: row = tid*2 >> 2
    // chunks c = tid*2, tid*2+1: row = c>>2, k4 = (c&3)*4
    const int bRowBase = tid >> 4;           // c>>5 for c = tid*2 -> tid>>4... compute inline

    float c[4][4][4] = {};

    auto load_tile = [&](int t, int s) {
        int k0 = t * BKT;
        #pragma unroll
        for (int cc = 0; cc < 2; cc++) {
            int id = tid * 2 + cc;
            int ar = id >> 2, ak = (id & 3) * 4;
            cpa16(&As[s][ar * ASTR + ak], Ab + (size_t)ar * K + k0 + ak);
            int br = id >> 5, bn = (id & 31) * 4;
            cpa16(&Bs[s][br * BSTR + bn], Bb + (size_t)(k0 + br) * N + bn);
        }
        asm volatile("cp.async.commit_group;\n");
    };
    (void)aRow0; (void)bRowBase;

    const int T = K / BKT;
    load_tile(0, 0);

    for (int t = 0; t < T; t++) {
        if (t + 1 < T) {
            load_tile(t + 1, (t + 1) & 1);
            asm volatile("cp.async.wait_group 1;\n");
        } else {
            asm volatile("cp.async.wait_group 0;\n");
        }
        __syncthreads();

        const float* Asb = As[t & 1];
        const float* Bsb = Bs[t & 1];

        #pragma unroll
        for (int ks = 0; ks < 2; ks++) {
            const int kc = ks * 8 + tig;
            uint32_t a[4][4], b[4][2];
            #pragma unroll
            for (int mi = 0; mi < 4; mi++) {
                int m0 = wm * 64 + mi * 16 + grp;
                a[mi][0] = __float_as_uint(Asb[(m0    ) * ASTR + kc    ]);
                a[mi][1] = __float_as_uint(Asb[(m0 + 8) * ASTR + kc    ]);
                a[mi][2] = __float_as_uint(Asb[(m0    ) * ASTR + kc + 4]);
                a[mi][3] = __float_as_uint(Asb[(m0 + 8) * ASTR + kc + 4]);
            }
            #pragma unroll
            for (int ni = 0; ni < 4; ni++) {
                int n0 = wn * 32 + ni * 8 + grp;
                b[ni][0] = __float_as_uint(Bsb[(ks * 8 + tig    ) * BSTR + n0]);
                b[ni][1] = __float_as_uint(Bsb[(ks * 8 + tig + 4) * BSTR + n0]);
            }
            #pragma unroll
            for (int mi = 0; mi < 4; mi++)
                #pragma unroll
                for (int ni = 0; ni < 4; ni++)
                    mma_tf32(c[mi][ni], a[mi][0], a[mi][1], a[mi][2], a[mi][3],
                             b[ni][0], b[ni][1]);
        }
        __syncthreads();
    }

    // epilogue
    #pragma unroll
    for (int mi = 0; mi < 4; mi++) {
        #pragma unroll
        for (int rr = 0; rr < 2; rr++) {
            int m = cRow * BM + wm * 64 + mi * 16 + grp + rr * 8;
            int outm = (mode == 3) ? map_row(m) : m;
            #pragma unroll
            for (int ni = 0; ni < 4; ni++) {
                int n = cCol * BN + wn * 32 + ni * 8 + tig * 2;
                float v0 = c[mi][ni][rr * 2 + 0] + bias[n];
                float v1 = c[mi][ni][rr * 2 + 1] + bias[n + 1];
                if (mode == 1) {
                    v0 = 0.5f * v0 * (1.0f + erff(v0 * 0.70710678118654752f));
                    v1 = 0.5f * v1 * (1.0f + erff(v1 * 0.70710678118654752f));
                } else if (mode == 2) {
                    v0 += res[(size_t)m * N + n];
                    v1 += res[(size_t)m * N + n + 1];
                } else if (mode == 3) {
                    v0 += res[(size_t)outm * N + n];
                    v1 += res[(size_t)outm * N + n + 1];
                }
                C[(size_t)outm * N + n]     = v0;
                C[(size_t)outm * N + n + 1] = v1;
            }
        }
    }
}

// Windowed attention: one block per (window, head).
// smem tiles padded to stride 33 -> conflict-free ks[j][d] access in scores.
#define HDP 33
__global__ __launch_bounds__(128) void attn_kernel(
    const float* __restrict__ q, const float* __restrict__ k,
    const float* __restrict__ v, const float* __restrict__ rel_table,
    const int* __restrict__ rel_index, float* __restrict__ ctx)
{
    __shared__ float qs[W2_][HDP];
    __shared__ float ks[W2_][HDP];
    __shared__ float vs[W2_][HDP];
    __shared__ float sc[W2_][W2_ + 1];
    __shared__ int   grp[W2_];

    int blk  = blockIdx.x;
    int head = blk & (HEADS_ - 1);
    int win  = blk >> 4;
    int w    = win & (NW_ - 1);
    int tid  = threadIdx.x;

    const size_t base = (size_t)win * W2_ * C_ + head * HD_;
    for (int idx = tid; idx < W2_ * HD_; idx += 128) {
        int t = idx >> 5, d = idx & 31;
        size_t off = base + (size_t)t * C_ + d;
        qs[t][d] = q[off];
        ks[t][d] = k[off];
        vs[t][d] = v[off];
    }
    if (tid < W2_) {
        int wh = w >> 2, ww = w & 3;
        int r = wh * WS_ + tid / WS_;
        int c = ww * WS_ + tid % WS_;
        int br = (r < HDIM - WS_) ? 0 : ((r < HDIM - SHIFT_) ? 1 : 2);
        int bc = (c < WDIM - WS_) ? 0 : ((c < WDIM - SHIFT_) ? 1 : 2);
        grp[tid] = br * 3 + bc;
    }
    __syncthreads();

    const float scale = 0.17677669529663687f; // 1/sqrt(32)
    for (int idx = tid; idx < W2_ * W2_; idx += 128) {
        int i = idx / W2_, j = idx - i * W2_;
        float acc = 0.0f;
        #pragma unroll
        for (int d = 0; d < HD_; d++) acc = fmaf(qs[i][d], ks[j][d], acc);
        float bias = rel_table[rel_index[idx] * HEADS_ + head];
        float mask = (grp[i] != grp[j]) ? -100.0f : 0.0f;
        sc[i][j] = acc * scale + bias + mask;
    }
    __syncthreads();

    if (tid < W2_) {
        float mx = -1e30f;
        #pragma unroll 7
        for (int j = 0; j < W2_; j++) mx = fmaxf(mx, sc[tid][j]);
        float sum = 0.0f;
        #pragma unroll 7
        for (int j = 0; j < W2_; j++) {
            float e = __expf(sc[tid][j] - mx);
            sc[tid][j] = e;
            sum += e;
        }
        float inv = 1.0f / sum;
        #pragma unroll 7
        for (int j = 0; j < W2_; j++) sc[tid][j] *= inv;
    }
    __syncthreads();

    for (int idx = tid; idx < W2_ * HD_; idx += 128) {
        int i = idx >> 5, d = idx & 31;
        float acc = 0.0f;
        #pragma unroll 7
        for (int j = 0; j < W2_; j++) acc = fmaf(sc[i][j], vs[j][d], acc);
        ctx[base + (size_t)i * C_ + d] = acc;
    }
}

extern "C" void kernel_launch(void* const* d_in, const int* in_sizes, int n_in,
                              void* d_out, int out_size)
{
    const float* x         = (const float*)d_in[0];
    const float* g1        = (const float*)d_in[1];
    const float* b1        = (const float*)d_in[2];
    const float* wq        = (const float*)d_in[3];
    const float* bq        = (const float*)d_in[4];
    const float* wk        = (const float*)d_in[5];
    const float* bk        = (const float*)d_in[6];
    const float* wv        = (const float*)d_in[7];
    const float* bv        = (const float*)d_in[8];
    const float* rel_table = (const float*)d_in[9];
    const float* wo        = (const float*)d_in[10];
    const float* bo        = (const float*)d_in[11];
    const float* g2        = (const float*)d_in[12];
    const float* b2        = (const float*)d_in[13];
    const float* wi        = (const float*)d_in[14];
    const float* bi        = (const float*)d_in[15];
    const float* w_out     = (const float*)d_in[16];
    const float* b_out     = (const float*)d_in[17];
    const int*   rel_index = (const int*)d_in[18];
    float* out = (float*)d_out;

    float *p_win, *p_q, *p_k, *p_v, *p_ctx, *p_x1, *p_h2, *p_mid;
    cudaGetSymbolAddress((void**)&p_win, g_win);
    cudaGetSymbolAddress((void**)&p_q,   g_q);
    cudaGetSymbolAddress((void**)&p_k,   g_k);
    cudaGetSymbolAddress((void**)&p_v,   g_v);
    cudaGetSymbolAddress((void**)&p_ctx, g_ctx);
    cudaGetSymbolAddress((void**)&p_x1,  g_x1);
    cudaGetSymbolAddress((void**)&p_h2,  g_h2);
    cudaGetSymbolAddress((void**)&p_mid, g_mid);

    // 1. LN1 + cyclic shift + window partition (gather)
    ln_kernel<<<MTOK, 128>>>(x, g1, b1, p_win, 1);

    // 2-4. QKV projections
    dim3 gC(C_ / BN, MTOK / BM);
    tgemm_kernel<<<gC, 256>>>(p_win, wq, bq, p_q, MTOK, C_, C_, 0, nullptr);
    tgemm_kernel<<<gC, 256>>>(p_win, wk, bk, p_k, MTOK, C_, C_, 0, nullptr);
    tgemm_kernel<<<gC, 256>>>(p_win, wv, bv, p_v, MTOK, C_, C_, 0, nullptr);

    // 5. windowed attention (scores + bias + mask + softmax + PV)
    attn_kernel<<<NWIN * HEADS_, 128>>>(p_q, p_k, p_v, rel_table, rel_index, p_ctx);

    // 6. output projection + window reverse + un-shift scatter + residual(x)
    tgemm_kernel<<<gC, 256>>>(p_ctx, wo, bo, p_x1, MTOK, C_, C_, 3, x);

    // 7. LN2
    ln_kernel<<<MTOK, 128>>>(p_x1, g2, b2, p_h2, 0);

    // 8. MLP up-projection + exact GELU
    dim3 gM(MLPD / BN, MTOK / BM);
    tgemm_kernel<<<gM, 256>>>(p_h2, wi, bi, p_mid, MTOK, MLPD, C_, 1, nullptr);

    // 9. MLP down-projection + residual(x1) -> final output
    tgemm_kernel<<<gC, 256>>>(p_mid, w_out, b_out, out, MTOK, C_, MLPD, 2, p_x1);
}

// round 5
// speedup vs baseline: 1.0009x; 1.0009x over previous
#include <cuda_runtime.h>
#include <math.h>
#include <stdint.h>

// Problem constants
#define BATCH   64
#define HDIM    28
#define WDIM    28
#define C_      512
#define HEADS_  16
#define WS_     7
#define SHIFT_  3
#define MLPD    2048
#define HD_     32
#define W2_     49
#define NW_     16
#define HW_     784
#define MTOK    50176   // BATCH*HW
#define NWIN    1024    // BATCH*NW

// Scratch (device globals: no allocation allowed in kernel_launch)
__device__ float g_win[MTOK * C_];
__device__ float g_q[MTOK * C_];
__device__ float g_k[MTOK * C_];
__device__ float g_v[MTOK * C_];
__device__ float g_ctx[MTOK * C_];
__device__ float g_x1[MTOK * C_];
__device__ float g_h2[MTOK * C_];
__device__ float g_mid[(size_t)MTOK * MLPD];

// Map window-partition row m -> token row in the unshifted [B,H*W] layout.
__device__ __forceinline__ int map_row(int m) {
    int bb  = m / HW_;
    int rem = m - bb * HW_;
    int w   = rem / W2_;
    int t   = rem - w * W2_;
    int wh = w >> 2, ww = w & 3;
    int th = t / WS_, tw = t - th * WS_;
    int r = wh * WS_ + th + SHIFT_; if (r >= HDIM) r -= HDIM;
    int c = ww * WS_ + tw + SHIFT_; if (c >= WDIM) c -= WDIM;
    return bb * HW_ + r * WDIM + c;
}

// LayerNorm over C=512, one block per token row.
__global__ __launch_bounds__(128) void ln_kernel(
    const float* __restrict__ in, const float* __restrict__ g,
    const float* __restrict__ b, float* __restrict__ out, int gather)
{
    int m = blockIdx.x;
    int src = gather ? map_row(m) : m;
    int tid = threadIdx.x;

    float4 xv = ((const float4*)(in + (size_t)src * C_))[tid];
    float s  = xv.x + xv.y + xv.z + xv.w;
    float s2 = xv.x*xv.x + xv.y*xv.y + xv.z*xv.z + xv.w*xv.w;
    #pragma unroll
    for (int off = 16; off; off >>= 1) {
        s  += __shfl_xor_sync(0xffffffffu, s,  off);
        s2 += __shfl_xor_sync(0xffffffffu, s2, off);
    }
    __shared__ float red[8];
    int wid = tid >> 5;
    if ((tid & 31) == 0) { red[wid] = s; red[4 + wid] = s2; }
    __syncthreads();
    s  = red[0] + red[1] + red[2] + red[3];
    s2 = red[4] + red[5] + red[6] + red[7];
    float mu   = s * (1.0f / C_);
    float var  = fmaf(-mu, mu, s2 * (1.0f / C_));
    float rstd = rsqrtf(var + 1e-5f);

    float4 gv = ((const float4*)g)[tid];
    float4 bv = ((const float4*)b)[tid];
    float4 o;
    o.x = (xv.x - mu) * rstd * gv.x + bv.x;
    o.y = (xv.y - mu) * rstd * gv.y + bv.y;
    o.z = (xv.z - mu) * rstd * gv.z + bv.z;
    o.w = (xv.w - mu) * rstd * gv.w + bv.w;
    ((float4*)(out + (size_t)m * C_))[tid] = o;
}

// ---------------------------------------------------------------------------
// TF32 tensor-core GEMM with cp.async double buffering.
// C[M,N] = A[M,K] @ B[K,N] + bias, epilogue modes.
// 256 threads = 8 warps (2 x 4), block tile 128x128, BK=16, warp tile 64x32.
// fp32 operands fed to mma.tf32 directly (HW truncation).
// mode 0: plain   mode 1: exact GELU   mode 2: += res[m]
// mode 3: scatter row via map_row(m), += res[out_row]
// ---------------------------------------------------------------------------
#define BM 128
#define BN 128
#define BKT 16
#define ASTR 20   // As row stride (floats): conflict-free (20g+t covers banks)
#define BSTR 136  // Bs row stride (floats): 136 mod 32 = 8 -> 8t+g covers banks

__device__ __forceinline__ void cpa16(void* smem_dst, const void* gsrc) {
    uint32_t s = (uint32_t)__cvta_generic_to_shared(smem_dst);
    asm volatile("cp.async.cg.shared.global [%0], [%1], 16;\n" :: "r"(s), "l"(gsrc));
}

__device__ __forceinline__ void mma_tf32(float c[4], uint32_t a0, uint32_t a1,
                                         uint32_t a2, uint32_t a3,
                                         uint32_t b0, uint32_t b1) {
    asm volatile(
        "mma.sync.aligned.m16n8k8.row.col.f32.tf32.tf32.f32 "
        "{%0,%1,%2,%3}, {%4,%5,%6,%7}, {%8,%9}, {%0,%1,%2,%3};"
        : "+f"(c[0]), "+f"(c[1]), "+f"(c[2]), "+f"(c[3])
        : "r"(a0), "r"(a1), "r"(a2), "r"(a3), "r"(b0), "r"(b1));
}

__global__ __launch_bounds__(256) void tgemm_kernel(
    const float* __restrict__ A, const float* __restrict__ Bm,
    const float* __restrict__ bias, float* __restrict__ C,
    int M, int N, int K, int mode, const float* __restrict__ res)
{
    __shared__ float As[2][BM * ASTR];
    __shared__ float Bs[2][BKT * BSTR];

    const int cRow = blockIdx.y, cCol = blockIdx.x;
    const int tid  = threadIdx.x;
    const int wid  = tid >> 5;
    const int lane = tid & 31;
    const int wm   = wid >> 2;       // 0..1
    const int wn   = wid & 3;        // 0..3
    const int grp  = lane >> 2;      // 0..7
    const int tig  = lane & 3;       // 0..3

    const float* Ab = A  + (size_t)cRow * BM * K;
    const float* Bb = Bm + (size_t)cCol * BN;

    // cp.async mapping: 2 A chunks + 2 B chunks per thread per tile
    const int aRow0 = tid >> 1;              // chunk0: row = tid*2 >> 2
    // chunks c = tid*2, tid*2+1: row = c>>2, k4 = (c&3)*4
    const int bRowBase = tid >> 4;           // c>>5 for c = tid*2 -> tid>>4... compute inline

    float c[4][4][4] = {};

    auto load_tile = [&](int t, int s) {
        int k0 = t * BKT;
        #pragma unroll
        for (int cc = 0; cc < 2; cc++) {
            int id = tid * 2 + cc;
            int ar = id >> 2, ak = (id & 3) * 4;
            cpa16(&As[s][ar * ASTR + ak], Ab + (size_t)ar * K + k0 + ak);
            int br = id >> 5, bn = (id & 31) * 4;
            cpa16(&Bs[s][br * BSTR + bn], Bb + (size_t)(k0 + br) * N + bn);
        }
        asm volatile("cp.async.commit_group;\n");
    };
    (void)aRow0; (void)bRowBase;

    const int T = K / BKT;
    load_tile(0, 0);

    for (int t = 0; t < T; t++) {
        if (t + 1 < T) {
            load_tile(t + 1, (t + 1) & 1);
            asm volatile("cp.async.wait_group 1;\n");
        } else {
            asm volatile("cp.async.wait_group 0;\n");
        }
        __syncthreads();

        const float* Asb = As[t & 1];
        const float* Bsb = Bs[t & 1];

        #pragma unroll
        for (int ks = 0; ks < 2; ks++) {
            const int kc = ks * 8 + tig;
            uint32_t a[4][4], b[4][2];
            #pragma unroll
            for (int mi = 0; mi < 4; mi++) {
                int m0 = wm * 64 + mi * 16 + grp;
                a[mi][0] = __float_as_uint(Asb[(m0    ) * ASTR + kc    ]);
                a[mi][1] = __float_as_uint(Asb[(m0 + 8) * ASTR + kc    ]);
                a[mi][2] = __float_as_uint(Asb[(m0    ) * ASTR + kc + 4]);
                a[mi][3] = __float_as_uint(Asb[(m0 + 8) * ASTR + kc + 4]);
            }
            #pragma unroll
            for (int ni = 0; ni < 4; ni++) {
                int n0 = wn * 32 + ni * 8 + grp;
                b[ni][0] = __float_as_uint(Bsb[(ks * 8 + tig    ) * BSTR + n0]);
                b[ni][1] = __float_as_uint(Bsb[(ks * 8 + tig + 4) * BSTR + n0]);
            }
            #pragma unroll
            for (int mi = 0; mi < 4; mi++)
                #pragma unroll
                for (int ni = 0; ni < 4; ni++)
                    mma_tf32(c[mi][ni], a[mi][0], a[mi][1], a[mi][2], a[mi][3],
                             b[ni][0], b[ni][1]);
        }
        __syncthreads();
    }

    // epilogue
    #pragma unroll
    for (int mi = 0; mi < 4; mi++) {
        #pragma unroll
        for (int rr = 0; rr < 2; rr++) {
            int m = cRow * BM + wm * 64 + mi * 16 + grp + rr * 8;
            int outm = (mode == 3) ? map_row(m) : m;
            #pragma unroll
            for (int ni = 0; ni < 4; ni++) {
                int n = cCol * BN + wn * 32 + ni * 8 + tig * 2;
                float v0 = c[mi][ni][rr * 2 + 0] + bias[n];
                float v1 = c[mi][ni][rr * 2 + 1] + bias[n + 1];
                if (mode == 1) {
                    v0 = 0.5f * v0 * (1.0f + erff(v0 * 0.70710678118654752f));
                    v1 = 0.5f * v1 * (1.0f + erff(v1 * 0.70710678118654752f));
                } else if (mode == 2) {
                    v0 += res[(size_t)m * N + n];
                    v1 += res[(size_t)m * N + n + 1];
                } else if (mode == 3) {
                    v0 += res[(size_t)outm * N + n];
                    v1 += res[(size_t)outm * N + n + 1];
                }
                C[(size_t)outm * N + n]     = v0;
                C[(size_t)outm * N + n + 1] = v1;
            }
        }
    }
}

// Windowed attention: one block per (window, head).
// smem tiles padded to stride 33 -> conflict-free ks[j][d] access in scores.
#define HDP 33
__global__ __launch_bounds__(128) void attn_kernel(
    const float* __restrict__ q, const float* __restrict__ k,
    const float* __restrict__ v, const float* __restrict__ rel_table,
    const int* __restrict__ rel_index, float* __restrict__ ctx)
{
    __shared__ float qs[W2_][HDP];
    __shared__ float ks[W2_][HDP];
    __shared__ float vs[W2_][HDP];
    __shared__ float sc[W2_][W2_ + 1];
    __shared__ int   grp[W2_];

    int blk  = blockIdx.x;
    int head = blk & (HEADS_ - 1);
    int win  = blk >> 4;
    int w    = win & (NW_ - 1);
    int tid  = threadIdx.x;

    const size_t base = (size_t)win * W2_ * C_ + head * HD_;
    for (int idx = tid; idx < W2_ * HD_; idx += 128) {
        int t = idx >> 5, d = idx & 31;
        size_t off = base + (size_t)t * C_ + d;
        qs[t][d] = q[off];
        ks[t][d] = k[off];
        vs[t][d] = v[off];
    }
    if (tid < W2_) {
        int wh = w >> 2, ww = w & 3;
        int r = wh * WS_ + tid / WS_;
        int c = ww * WS_ + tid % WS_;
        int br = (r < HDIM - WS_) ? 0 : ((r < HDIM - SHIFT_) ? 1 : 2);
        int bc = (c < WDIM - WS_) ? 0 : ((c < WDIM - SHIFT_) ? 1 : 2);
        grp[tid] = br * 3 + bc;
    }
    __syncthreads();

    const float scale = 0.17677669529663687f; // 1/sqrt(32)
    for (int idx = tid; idx < W2_ * W2_; idx += 128) {
        int i = idx / W2_, j = idx - i * W2_;
        float acc = 0.0f;
        #pragma unroll
        for (int d = 0; d < HD_; d++) acc = fmaf(qs[i][d], ks[j][d], acc);
        float bias = rel_table[rel_index[idx] * HEADS_ + head];
        float mask = (grp[i] != grp[j]) ? -100.0f : 0.0f;
        sc[i][j] = acc * scale + bias + mask;
    }
    __syncthreads();

    if (tid < W2_) {
        float mx = -1e30f;
        #pragma unroll 7
        for (int j = 0; j < W2_; j++) mx = fmaxf(mx, sc[tid][j]);
        float sum = 0.0f;
        #pragma unroll 7
        for (int j = 0; j < W2_; j++) {
            float e = __expf(sc[tid][j] - mx);
            sc[tid][j] = e;
            sum += e;
        }
        float inv = 1.0f / sum;
        #pragma unroll 7
        for (int j = 0; j < W2_; j++) sc[tid][j] *= inv;
    }
    __syncthreads();

    for (int idx = tid; idx < W2_ * HD_; idx += 128) {
        int i = idx >> 5, d = idx & 31;
        float acc = 0.0f;
        #pragma unroll 7
        for (int j = 0; j < W2_; j++) acc = fmaf(sc[i][j], vs[j][d], acc);
        ctx[base + (size_t)i * C_ + d] = acc;
    }
}

extern "C" void kernel_launch(void* const* d_in, const int* in_sizes, int n_in,
                              void* d_out, int out_size)
{
    const float* x         = (const float*)d_in[0];
    const float* g1        = (const float*)d_in[1];
    const float* b1        = (const float*)d_in[2];
    const float* wq        = (const float*)d_in[3];
    const float* bq        = (const float*)d_in[4];
    const float* wk        = (const float*)d_in[5];
    const float* bk        = (const float*)d_in[6];
    const float* wv        = (const float*)d_in[7];
    const float* bv        = (const float*)d_in[8];
    const float* rel_table = (const float*)d_in[9];
    const float* wo        = (const float*)d_in[10];
    const float* bo        = (const float*)d_in[11];
    const float* g2        = (const float*)d_in[12];
    const float* b2        = (const float*)d_in[13];
    const float* wi        = (const float*)d_in[14];
    const float* bi        = (const float*)d_in[15];
    const float* w_out     = (const float*)d_in[16];
    const float* b_out     = (const float*)d_in[17];
    const int*   rel_index = (const int*)d_in[18];
    float* out = (float*)d_out;

    float *p_win, *p_q, *p_k, *p_v, *p_ctx, *p_x1, *p_h2, *p_mid;
    cudaGetSymbolAddress((void**)&p_win, g_win);
    cudaGetSymbolAddress((void**)&p_q,   g_q);
    cudaGetSymbolAddress((void**)&p_k,   g_k);
    cudaGetSymbolAddress((void**)&p_v,   g_v);
    cudaGetSymbolAddress((void**)&p_ctx, g_ctx);
    cudaGetSymbolAddress((void**)&p_x1,  g_x1);
    cudaGetSymbolAddress((void**)&p_h2,  g_h2);
    cudaGetSymbolAddress((void**)&p_mid, g_mid);

    // 1. LN1 + cyclic shift + window partition (gather)
    ln_kernel<<<MTOK, 128>>>(x, g1, b1, p_win, 1);

    // 2-4. QKV projections
    dim3 gC(C_ / BN, MTOK / BM);
    tgemm_kernel<<<gC, 256>>>(p_win, wq, bq, p_q, MTOK, C_, C_, 0, nullptr);
    tgemm_kernel<<<gC, 256>>>(p_win, wk, bk, p_k, MTOK, C_, C_, 0, nullptr);
    tgemm_kernel<<<gC, 256>>>(p_win, wv, bv, p_v, MTOK, C_, C_, 0, nullptr);

    // 5. windowed attention (scores + bias + mask + softmax + PV)
    attn_kernel<<<NWIN * HEADS_, 128>>>(p_q, p_k, p_v, rel_table, rel_index, p_ctx);

    // 6. output projection + window reverse + un-shift scatter + residual(x)
    tgemm_kernel<<<gC, 256>>>(p_ctx, wo, bo, p_x1, MTOK, C_, C_, 3, x);

    // 7. LN2
    ln_kernel<<<MTOK, 128>>>(p_x1, g2, b2, p_h2, 0);

    // 8. MLP up-projection + exact GELU
    dim3 gM(MLPD / BN, MTOK / BM);
    tgemm_kernel<<<gM, 256>>>(p_h2, wi, bi, p_mid, MTOK, MLPD, C_, 1, nullptr);

    // 9. MLP down-projection + residual(x1) -> final output
    tgemm_kernel<<<gC, 256>>>(p_mid, w_out, b_out, out, MTOK, C_, MLPD, 2, p_x1);
}

// round 6
// speedup vs baseline: 1.0013x; 1.0003x over previous
#include <cuda_runtime.h>
#include <math.h>
#include <stdint.h>

// Problem constants
#define BATCH   64
#define HDIM    28
#define WDIM    28
#define C_      512
#define HEADS_  16
#define WS_     7
#define SHIFT_  3
#define MLPD    2048
#define HD_     32
#define W2_     49
#define NW_     16
#define HW_     784
#define MTOK    50176   // BATCH*HW
#define NWIN    1024    // BATCH*NW

// Scratch (device globals: no allocation allowed in kernel_launch)
__device__ float g_win[MTOK * C_];
__device__ float g_q[MTOK * C_];
__device__ float g_k[MTOK * C_];
__device__ float g_v[MTOK * C_];
__device__ float g_ctx[MTOK * C_];
__device__ float g_x1[MTOK * C_];
__device__ float g_h2[MTOK * C_];
__device__ float g_mid[(size_t)MTOK * MLPD];

// Map window-partition row m -> token row in the unshifted [B,H*W] layout.
__device__ __forceinline__ int map_row(int m) {
    int bb  = m / HW_;
    int rem = m - bb * HW_;
    int w   = rem / W2_;
    int t   = rem - w * W2_;
    int wh = w >> 2, ww = w & 3;
    int th = t / WS_, tw = t - th * WS_;
    int r = wh * WS_ + th + SHIFT_; if (r >= HDIM) r -= HDIM;
    int c = ww * WS_ + tw + SHIFT_; if (c >= WDIM) c -= WDIM;
    return bb * HW_ + r * WDIM + c;
}

// LayerNorm over C=512, one block per token row.
__global__ __launch_bounds__(128) void ln_kernel(
    const float* __restrict__ in, const float* __restrict__ g,
    const float* __restrict__ b, float* __restrict__ out, int gather)
{
    int m = blockIdx.x;
    int src = gather ? map_row(m) : m;
    int tid = threadIdx.x;

    float4 xv = ((const float4*)(in + (size_t)src * C_))[tid];
    float s  = xv.x + xv.y + xv.z + xv.w;
    float s2 = xv.x*xv.x + xv.y*xv.y + xv.z*xv.z + xv.w*xv.w;
    #pragma unroll
    for (int off = 16; off; off >>= 1) {
        s  += __shfl_xor_sync(0xffffffffu, s,  off);
        s2 += __shfl_xor_sync(0xffffffffu, s2, off);
    }
    __shared__ float red[8];
    int wid = tid >> 5;
    if ((tid & 31) == 0) { red[wid] = s; red[4 + wid] = s2; }
    __syncthreads();
    s  = red[0] + red[1] + red[2] + red[3];
    s2 = red[4] + red[5] + red[6] + red[7];
    float mu   = s * (1.0f / C_);
    float var  = fmaf(-mu, mu, s2 * (1.0f / C_));
    float rstd = rsqrtf(var + 1e-5f);

    float4 gv = ((const float4*)g)[tid];
    float4 bv = ((const float4*)b)[tid];
    float4 o;
    o.x = (xv.x - mu) * rstd * gv.x + bv.x;
    o.y = (xv.y - mu) * rstd * gv.y + bv.y;
    o.z = (xv.z - mu) * rstd * gv.z + bv.z;
    o.w = (xv.w - mu) * rstd * gv.w + bv.w;
    ((float4*)(out + (size_t)m * C_))[tid] = o;
}

// ---------------------------------------------------------------------------
// TF32 tensor-core GEMM with cp.async double buffering.
// C[M,N] = A[M,K] @ B[K,N] + bias, epilogue modes.
// 256 threads = 8 warps (2 x 4), block tile 128x128, BK=16, warp tile 64x32.
// fp32 operands fed to mma.tf32 directly (HW truncation).
// mode 0: plain   mode 1: exact GELU   mode 2: += res[m]
// mode 3: scatter row via map_row(m), += res[out_row]
// ---------------------------------------------------------------------------
#define BM 128
#define BN 128
#define BKT 16
#define ASTR 20   // As row stride (floats): conflict-free (20g+t covers banks)
#define BSTR 136  // Bs row stride (floats): 136 mod 32 = 8 -> 8t+g covers banks

__device__ __forceinline__ void cpa16(void* smem_dst, const void* gsrc) {
    uint32_t s = (uint32_t)__cvta_generic_to_shared(smem_dst);
    asm volatile("cp.async.cg.shared.global [%0], [%1], 16;\n" :: "r"(s), "l"(gsrc));
}

__device__ __forceinline__ void mma_tf32(float c[4], uint32_t a0, uint32_t a1,
                                         uint32_t a2, uint32_t a3,
                                         uint32_t b0, uint32_t b1) {
    asm volatile(
        "mma.sync.aligned.m16n8k8.row.col.f32.tf32.tf32.f32 "
        "{%0,%1,%2,%3}, {%4,%5,%6,%7}, {%8,%9}, {%0,%1,%2,%3};"
        : "+f"(c[0]), "+f"(c[1]), "+f"(c[2]), "+f"(c[3])
        : "r"(a0), "r"(a1), "r"(a2), "r"(a3), "r"(b0), "r"(b1));
}

__global__ __launch_bounds__(256) void tgemm_kernel(
    const float* __restrict__ A, const float* __restrict__ Bm,
    const float* __restrict__ bias, float* __restrict__ C,
    int M, int N, int K, int mode, const float* __restrict__ res)
{
    __shared__ float As[2][BM * ASTR];
    __shared__ float Bs[2][BKT * BSTR];

    const int cRow = blockIdx.y, cCol = blockIdx.x;
    const int tid  = threadIdx.x;
    const int wid  = tid >> 5;
    const int lane = tid & 31;
    const int wm   = wid >> 2;       // 0..1
    const int wn   = wid & 3;        // 0..3
    const int grp  = lane >> 2;      // 0..7
    const int tig  = lane & 3;       // 0..3

    const float* Ab = A  + (size_t)cRow * BM * K;
    const float* Bb = Bm + (size_t)cCol * BN;

    // cp.async mapping: 2 A chunks + 2 B chunks per thread per tile
    const int aRow0 = tid >> 1;              // chunk0: row = tid*2 >> 2
    // chunks c = tid*2, tid*2+1: row = c>>2, k4 = (c&3)*4
    const int bRowBase = tid >> 4;           // c>>5 for c = tid*2 -> tid>>4... compute inline

    float c[4][4][4] = {};

    auto load_tile = [&](int t, int s) {
        int k0 = t * BKT;
        #pragma unroll
        for (int cc = 0; cc < 2; cc++) {
            int id = tid * 2 + cc;
            int ar = id >> 2, ak = (id & 3) * 4;
            cpa16(&As[s][ar * ASTR + ak], Ab + (size_t)ar * K + k0 + ak);
            int br = id >> 5, bn = (id & 31) * 4;
            cpa16(&Bs[s][br * BSTR + bn], Bb + (size_t)(k0 + br) * N + bn);
        }
        asm volatile("cp.async.commit_group;\n");
    };
    (void)aRow0; (void)bRowBase;

    const int T = K / BKT;
    load_tile(0, 0);

    for (int t = 0; t < T; t++) {
        if (t + 1 < T) {
            load_tile(t + 1, (t + 1) & 1);
            asm volatile("cp.async.wait_group 1;\n");
        } else {
            asm volatile("cp.async.wait_group 0;\n");
        }
        __syncthreads();

        const float* Asb = As[t & 1];
        const float* Bsb = Bs[t & 1];

        #pragma unroll
        for (int ks = 0; ks < 2; ks++) {
            const int kc = ks * 8 + tig;
            uint32_t a[4][4], b[4][2];
            #pragma unroll
            for (int mi = 0; mi < 4; mi++) {
                int m0 = wm * 64 + mi * 16 + grp;
                a[mi][0] = __float_as_uint(Asb[(m0    ) * ASTR + kc    ]);
                a[mi][1] = __float_as_uint(Asb[(m0 + 8) * ASTR + kc    ]);
                a[mi][2] = __float_as_uint(Asb[(m0    ) * ASTR + kc + 4]);
                a[mi][3] = __float_as_uint(Asb[(m0 + 8) * ASTR + kc + 4]);
            }
            #pragma unroll
            for (int ni = 0; ni < 4; ni++) {
                int n0 = wn * 32 + ni * 8 + grp;
                b[ni][0] = __float_as_uint(Bsb[(ks * 8 + tig    ) * BSTR + n0]);
                b[ni][1] = __float_as_uint(Bsb[(ks * 8 + tig + 4) * BSTR + n0]);
            }
            #pragma unroll
            for (int mi = 0; mi < 4; mi++)
                #pragma unroll
                for (int ni = 0; ni < 4; ni++)
                    mma_tf32(c[mi][ni], a[mi][0], a[mi][1], a[mi][2], a[mi][3],
                             b[ni][0], b[ni][1]);
        }
        __syncthreads();
    }

    // epilogue
    #pragma unroll
    for (int mi = 0; mi < 4; mi++) {
        #pragma unroll
        for (int rr = 0; rr < 2; rr++) {
            int m = cRow * BM + wm * 64 + mi * 16 + grp + rr * 8;
            int outm = (mode == 3) ? map_row(m) : m;
            #pragma unroll
            for (int ni = 0; ni < 4; ni++) {
                int n = cCol * BN + wn * 32 + ni * 8 + tig * 2;
                float v0 = c[mi][ni][rr * 2 + 0] + bias[n];
                float v1 = c[mi][ni][rr * 2 + 1] + bias[n + 1];
                if (mode == 1) {
                    v0 = 0.5f * v0 * (1.0f + erff(v0 * 0.70710678118654752f));
                    v1 = 0.5f * v1 * (1.0f + erff(v1 * 0.70710678118654752f));
                } else if (mode == 2) {
                    v0 += res[(size_t)m * N + n];
                    v1 += res[(size_t)m * N + n + 1];
                } else if (mode == 3) {
                    v0 += res[(size_t)outm * N + n];
                    v1 += res[(size_t)outm * N + n + 1];
                }
                C[(size_t)outm * N + n]     = v0;
                C[(size_t)outm * N + n + 1] = v1;
            }
        }
    }
}

// Windowed attention: one block per (window, head).
// smem tiles padded to stride 33 -> conflict-free ks[j][d] access in scores.
#define HDP 33
__global__ __launch_bounds__(128) void attn_kernel(
    const float* __restrict__ q, const float* __restrict__ k,
    const float* __restrict__ v, const float* __restrict__ rel_table,
    const int* __restrict__ rel_index, float* __restrict__ ctx)
{
    __shared__ float qs[W2_][HDP];
    __shared__ float ks[W2_][HDP];
    __shared__ float vs[W2_][HDP];
    __shared__ float sc[W2_][W2_ + 1];
    __shared__ int   grp[W2_];

    int blk  = blockIdx.x;
    int head = blk & (HEADS_ - 1);
    int win  = blk >> 4;
    int w    = win & (NW_ - 1);
    int tid  = threadIdx.x;

    const size_t base = (size_t)win * W2_ * C_ + head * HD_;
    for (int idx = tid; idx < W2_ * HD_; idx += 128) {
        int t = idx >> 5, d = idx & 31;
        size_t off = base + (size_t)t * C_ + d;
        qs[t][d] = q[off];
        ks[t][d] = k[off];
        vs[t][d] = v[off];
    }
    if (tid < W2_) {
        int wh = w >> 2, ww = w & 3;
        int r = wh * WS_ + tid / WS_;
        int c = ww * WS_ + tid % WS_;
        int br = (r < HDIM - WS_) ? 0 : ((r < HDIM - SHIFT_) ? 1 : 2);
        int bc = (c < WDIM - WS_) ? 0 : ((c < WDIM - SHIFT_) ? 1 : 2);
        grp[tid] = br * 3 + bc;
    }
    __syncthreads();

    const float scale = 0.17677669529663687f; // 1/sqrt(32)
    for (int idx = tid; idx < W2_ * W2_; idx += 128) {
        int i = idx / W2_, j = idx - i * W2_;
        float acc = 0.0f;
        #pragma unroll
        for (int d = 0; d < HD_; d++) acc = fmaf(qs[i][d], ks[j][d], acc);
        float bias = rel_table[rel_index[idx] * HEADS_ + head];
        float mask = (grp[i] != grp[j]) ? -100.0f : 0.0f;
        sc[i][j] = acc * scale + bias + mask;
    }
    __syncthreads();

    if (tid < W2_) {
        float mx = -1e30f;
        #pragma unroll 7
        for (int j = 0; j < W2_; j++) mx = fmaxf(mx, sc[tid][j]);
        float sum = 0.0f;
        #pragma unroll 7
        for (int j = 0; j < W2_; j++) {
            float e = __expf(sc[tid][j] - mx);
            sc[tid][j] = e;
            sum += e;
        }
        float inv = 1.0f / sum;
        #pragma unroll 7
        for (int j = 0; j < W2_; j++) sc[tid][j] *= inv;
    }
    __syncthreads();

    for (int idx = tid; idx < W2_ * HD_; idx += 128) {
        int i = idx >> 5, d = idx & 31;
        float acc = 0.0f;
        #pragma unroll 7
        for (int j = 0; j < W2_; j++) acc = fmaf(sc[i][j], vs[j][d], acc);
        ctx[base + (size_t)i * C_ + d] = acc;
    }
}

extern "C" void kernel_launch(void* const* d_in, const int* in_sizes, int n_in,
                              void* d_out, int out_size)
{
    const float* x         = (const float*)d_in[0];
    const float* g1        = (const float*)d_in[1];
    const float* b1        = (const float*)d_in[2];
    const float* wq        = (const float*)d_in[3];
    const float* bq        = (const float*)d_in[4];
    const float* wk        = (const float*)d_in[5];
    const float* bk        = (const float*)d_in[6];
    const float* wv        = (const float*)d_in[7];
    const float* bv        = (const float*)d_in[8];
    const float* rel_table = (const float*)d_in[9];
    const float* wo        = (const float*)d_in[10];
    const float* bo        = (const float*)d_in[11];
    const float* g2        = (const float*)d_in[12];
    const float* b2        = (const float*)d_in[13];
    const float* wi        = (const float*)d_in[14];
    const float* bi        = (const float*)d_in[15];
    const float* w_out     = (const float*)d_in[16];
    const float* b_out     = (const float*)d_in[17];
    const int*   rel_index = (const int*)d_in[18];
    float* out = (float*)d_out;

    float *p_win, *p_q, *p_k, *p_v, *p_ctx, *p_x1, *p_h2, *p_mid;
    cudaGetSymbolAddress((void**)&p_win, g_win);
    cudaGetSymbolAddress((void**)&p_q,   g_q);
    cudaGetSymbolAddress((void**)&p_k,   g_k);
    cudaGetSymbolAddress((void**)&p_v,   g_v);
    cudaGetSymbolAddress((void**)&p_ctx, g_ctx);
    cudaGetSymbolAddress((void**)&p_x1,  g_x1);
    cudaGetSymbolAddress((void**)&p_h2,  g_h2);
    cudaGetSymbolAddress((void**)&p_mid, g_mid);

    // 1. LN1 + cyclic shift + window partition (gather)
    ln_kernel<<<MTOK, 128>>>(x, g1, b1, p_win, 1);

    // 2-4. QKV projections
    dim3 gC(C_ / BN, MTOK / BM);
    tgemm_kernel<<<gC, 256>>>(p_win, wq, bq, p_q, MTOK, C_, C_, 0, nullptr);
    tgemm_kernel<<<gC, 256>>>(p_win, wk, bk, p_k, MTOK, C_, C_, 0, nullptr);
    tgemm_kernel<<<gC, 256>>>(p_win, wv, bv, p_v, MTOK, C_, C_, 0, nullptr);

    // 5. windowed attention (scores + bias + mask + softmax + PV)
    attn_kernel<<<NWIN * HEADS_, 128>>>(p_q, p_k, p_v, rel_table, rel_index, p_ctx);

    // 6. output projection + window reverse + un-shift scatter + residual(x)
    tgemm_kernel<<<gC, 256>>>(p_ctx, wo, bo, p_x1, MTOK, C_, C_, 3, x);

    // 7. LN2
    ln_kernel<<<MTOK, 128>>>(p_x1, g2, b2, p_h2, 0);

    // 8. MLP up-projection + exact GELU
    dim3 gM(MLPD / BN, MTOK / BM);
    tgemm_kernel<<<gM, 256>>>(p_h2, wi, bi, p_mid, MTOK, MLPD, C_, 1, nullptr);

    // 9. MLP down-projection + residual(x1) -> final output
    tgemm_kernel<<<gC, 256>>>(p_mid, w_out, b_out, out, MTOK, C_, MLPD, 2, p_x1);
}

// round 8
// speedup vs baseline: 1.0142x; 1.0130x over previous
#include <cuda_runtime.h>
#include <math.h>
#include <stdint.h>

// Problem constants
#define BATCH   64
#define HDIM    28
#define WDIM    28
#define C_      512
#define HEADS_  16
#define WS_     7
#define SHIFT_  3
#define MLPD    2048
#define HD_     32
#define W2_     49
#define NW_     16
#define HW_     784
#define MTOK    50176   // BATCH*HW
#define NWIN    1024    // BATCH*NW
#define C3      1536    // 3*C_ fused qkv width

// Scratch (device globals: no allocation allowed in kernel_launch)
__device__ float g_win[MTOK * C_];
__device__ float g_ctx[MTOK * C_];
__device__ float g_x1[MTOK * C_];
__device__ float g_h2[MTOK * C_];
__device__ float g_mid[(size_t)MTOK * MLPD];   // also holds fused qkv [MTOK][1536]
__device__ float g_wcat[C_ * C3];              // [K=512][N=1536] concat of wq|wk|wv
__device__ float g_bcat[C3];

// Map window-partition row m -> token row in the unshifted [B,H*W] layout.
__device__ __forceinline__ int map_row(int m) {
    int bb  = m / HW_;
    int rem = m - bb * HW_;
    int w   = rem / W2_;
    int t   = rem - w * W2_;
    int wh = w >> 2, ww = w & 3;
    int th = t / WS_, tw = t - th * WS_;
    int r = wh * WS_ + th + SHIFT_; if (r >= HDIM) r -= HDIM;
    int c = ww * WS_ + tw + SHIFT_; if (c >= WDIM) c -= WDIM;
    return bb * HW_ + r * WDIM + c;
}

// Concat qkv weights/biases: wcat[k][j*512+n] = w_j[k][n]
__global__ __launch_bounds__(256) void concat_kernel(
    const float* __restrict__ wq, const float* __restrict__ wk,
    const float* __restrict__ wv, const float* __restrict__ bq,
    const float* __restrict__ bk, const float* __restrict__ bv,
    float* __restrict__ wcat, float* __restrict__ bcat)
{
    int idx = blockIdx.x * 256 + threadIdx.x;
    if (idx < C_ * C_) {
        int k = idx / C_, n = idx - k * C_;
        wcat[(size_t)k * C3 + n        ] = wq[idx];
        wcat[(size_t)k * C3 + n + C_   ] = wk[idx];
        wcat[(size_t)k * C3 + n + 2*C_ ] = wv[idx];
    }
    if (idx < C_) {
        bcat[idx        ] = bq[idx];
        bcat[idx + C_   ] = bk[idx];
        bcat[idx + 2*C_ ] = bv[idx];
    }
}

// LayerNorm over C=512, one block per token row.
__global__ __launch_bounds__(128) void ln_kernel(
    const float* __restrict__ in, const float* __restrict__ g,
    const float* __restrict__ b, float* __restrict__ out, int gather)
{
    int m = blockIdx.x;
    int src = gather ? map_row(m) : m;
    int tid = threadIdx.x;

    float4 xv = ((const float4*)(in + (size_t)src * C_))[tid];
    float s  = xv.x + xv.y + xv.z + xv.w;
    float s2 = xv.x*xv.x + xv.y*xv.y + xv.z*xv.z + xv.w*xv.w;
    #pragma unroll
    for (int off = 16; off; off >>= 1) {
        s  += __shfl_xor_sync(0xffffffffu, s,  off);
        s2 += __shfl_xor_sync(0xffffffffu, s2, off);
    }
    __shared__ float red[8];
    int wid = tid >> 5;
    if ((tid & 31) == 0) { red[wid] = s; red[4 + wid] = s2; }
    __syncthreads();
    s  = red[0] + red[1] + red[2] + red[3];
    s2 = red[4] + red[5] + red[6] + red[7];
    float mu   = s * (1.0f / C_);
    float var  = fmaf(-mu, mu, s2 * (1.0f / C_));
    float rstd = rsqrtf(var + 1e-5f);

    float4 gv = ((const float4*)g)[tid];
    float4 bv = ((const float4*)b)[tid];
    float4 o;
    o.x = (xv.x - mu) * rstd * gv.x + bv.x;
    o.y = (xv.y - mu) * rstd * gv.y + bv.y;
    o.z = (xv.z - mu) * rstd * gv.z + bv.z;
    o.w = (xv.w - mu) * rstd * gv.w + bv.w;
    ((float4*)(out + (size_t)m * C_))[tid] = o;
}

// ---------------------------------------------------------------------------
// TF32 tensor-core GEMM, 4-stage cp.async pipeline, one sync per stage.
// C[M,N] = A[M,K] @ B[K,N] + bias, epilogue modes.
// 256 threads = 8 warps (2 x 4), block tile 128x128, BK=16, warp tile 64x32.
// fp32 operands fed to mma.tf32 directly (HW truncation).
// mode 0: plain   mode 1: exact GELU   mode 2: += res[m]
// mode 3: scatter row via map_row(m), += res[out_row]
// ---------------------------------------------------------------------------
#define BM 128
#define BN 128
#define BKT 16
#define ASTR 20    // As row stride (floats): conflict-free
#define BSTR 136   // Bs row stride (floats): 136 mod 32 = 8 -> conflict-free
#define NSTAGE 4
#define AFLOATS (BM * ASTR)            // 2560
#define BFLOATS (BKT * BSTR)           // 2176
#define STAGEF  (AFLOATS + BFLOATS)    // 4736 floats = 18944 B
#define SMEM_GEMM (NSTAGE * STAGEF * 4)  // 75776 B

__device__ __forceinline__ void cpa16(uint32_t smem_dst, const void* gsrc) {
    asm volatile("cp.async.cg.shared.global [%0], [%1], 16;\n"
                 :: "r"(smem_dst), "l"(gsrc));
}

__device__ __forceinline__ void mma_tf32(float c[4], uint32_t a0, uint32_t a1,
                                         uint32_t a2, uint32_t a3,
                                         uint32_t b0, uint32_t b1) {
    asm volatile(
        "mma.sync.aligned.m16n8k8.row.col.f32.tf32.tf32.f32 "
        "{%0,%1,%2,%3}, {%4,%5,%6,%7}, {%8,%9}, {%0,%1,%2,%3};"
        : "+f"(c[0]), "+f"(c[1]), "+f"(c[2]), "+f"(c[3])
        : "r"(a0), "r"(a1), "r"(a2), "r"(a3), "r"(b0), "r"(b1));
}

__global__ __launch_bounds__(256) void tgemm_kernel(
    const float* __restrict__ A, const float* __restrict__ Bm,
    const float* __restrict__ bias, float* __restrict__ C,
    int M, int N, int K, int mode, const float* __restrict__ res)
{
    extern __shared__ float sm[];

    const int cRow = blockIdx.y, cCol = blockIdx.x;
    const int tid  = threadIdx.x;
    const int wid  = tid >> 5;
    const int lane = tid & 31;
    const int wm   = wid >> 2;       // 0..1
    const int wn   = wid & 3;        // 0..3
    const int grp  = lane >> 2;      // 0..7
    const int tig  = lane & 3;       // 0..3

    const float* Ab = A  + (size_t)cRow * BM * K;
    const float* Bb = Bm + (size_t)cCol * BN;

    uint32_t smem_base = (uint32_t)__cvta_generic_to_shared(sm);

    float c[4][4][4] = {};

    // chunk mapping: 2 A float4s + 2 B float4s per thread per stage
    auto load_tile = [&](int t, int s) {
        const int k0 = t * BKT;
        uint32_t abase = smem_base + (uint32_t)(s * STAGEF * 4);
        uint32_t bbase = abase + AFLOATS * 4;
        #pragma unroll
        for (int cc = 0; cc < 2; cc++) {
            int id = tid * 2 + cc;
            int ar = id >> 2, ak = (id & 3) * 4;
            cpa16(abase + (uint32_t)((ar * ASTR + ak) * 4),
                  Ab + (size_t)ar * K + k0 + ak);
            int br = id >> 5, bn = (id & 31) * 4;
            cpa16(bbase + (uint32_t)((br * BSTR + bn) * 4),
                  Bb + (size_t)(k0 + br) * N + bn);
        }
    };

    const int T = K / BKT;
    #pragma unroll
    for (int s = 0; s < NSTAGE - 1; s++) {
        load_tile(s, s);
        asm volatile("cp.async.commit_group;");
    }

    for (int i = 0; i < T; i++) {
        asm volatile("cp.async.wait_group %0;" :: "n"(NSTAGE - 2));
        __syncthreads();

        // issue loads for stage i+3 (reuses buffer of stage i-1; safe after sync)
        if (i + NSTAGE - 1 < T) load_tile(i + NSTAGE - 1, (i + NSTAGE - 1) & (NSTAGE - 1));
        asm volatile("cp.async.commit_group;");

        const float* Asb = sm + (i & (NSTAGE - 1)) * STAGEF;
        const float* Bsb = Asb + AFLOATS;

        #pragma unroll
        for (int ks = 0; ks < 2; ks++) {
            const int kc = ks * 8 + tig;
            uint32_t a[4][4], b[4][2];
            #pragma unroll
            for (int mi = 0; mi < 4; mi++) {
                int m0 = wm * 64 + mi * 16 + grp;
                a[mi][0] = __float_as_uint(Asb[(m0    ) * ASTR + kc    ]);
                a[mi][1] = __float_as_uint(Asb[(m0 + 8) * ASTR + kc    ]);
                a[mi][2] = __float_as_uint(Asb[(m0    ) * ASTR + kc + 4]);
                a[mi][3] = __float_as_uint(Asb[(m0 + 8) * ASTR + kc + 4]);
            }
            #pragma unroll
            for (int ni = 0; ni < 4; ni++) {
                int n0 = wn * 32 + ni * 8 + grp;
                b[ni][0] = __float_as_uint(Bsb[(ks * 8 + tig    ) * BSTR + n0]);
                b[ni][1] = __float_as_uint(Bsb[(ks * 8 + tig + 4) * BSTR + n0]);
            }
            #pragma unroll
            for (int mi = 0; mi < 4; mi++)
                #pragma unroll
                for (int ni = 0; ni < 4; ni++)
                    mma_tf32(c[mi][ni], a[mi][0], a[mi][1], a[mi][2], a[mi][3],
                             b[ni][0], b[ni][1]);
        }
    }

    // epilogue
    #pragma unroll
    for (int mi = 0; mi < 4; mi++) {
        #pragma unroll
        for (int rr = 0; rr < 2; rr++) {
            int m = cRow * BM + wm * 64 + mi * 16 + grp + rr * 8;
            int outm = (mode == 3) ? map_row(m) : m;
            #pragma unroll
            for (int ni = 0; ni < 4; ni++) {
                int n = cCol * BN + wn * 32 + ni * 8 + tig * 2;
                float v0 = c[mi][ni][rr * 2 + 0] + bias[n];
                float v1 = c[mi][ni][rr * 2 + 1] + bias[n + 1];
                if (mode == 1) {
                    v0 = 0.5f * v0 * (1.0f + erff(v0 * 0.70710678118654752f));
                    v1 = 0.5f * v1 * (1.0f + erff(v1 * 0.70710678118654752f));
                } else if (mode == 2) {
                    v0 += res[(size_t)m * N + n];
                    v1 += res[(size_t)m * N + n + 1];
                } else if (mode == 3) {
                    v0 += res[(size_t)outm * N + n];
                    v1 += res[(size_t)outm * N + n + 1];
                }
                C[(size_t)outm * N + n]     = v0;
                C[(size_t)outm * N + n + 1] = v1;
            }
        }
    }
}

// Windowed attention: one block per (window, head). Reads fused qkv buffer
// with row stride 1536 (q at +0, k at +512, v at +1024). Conflict-free smem.
#define HDP 33
__global__ __launch_bounds__(128) void attn_kernel(
    const float* __restrict__ qkv, const float* __restrict__ rel_table,
    const int* __restrict__ rel_index, float* __restrict__ ctx)
{
    __shared__ float qs[W2_][HDP];
    __shared__ float ks[W2_][HDP];
    __shared__ float vs[W2_][HDP];
    __shared__ float sc[W2_][W2_ + 1];
    __shared__ int   grp[W2_];

    int blk  = blockIdx.x;
    int head = blk & (HEADS_ - 1);
    int win  = blk >> 4;
    int w    = win & (NW_ - 1);
    int tid  = threadIdx.x;

    const size_t qbase = (size_t)win * W2_ * C3 + head * HD_;
    for (int idx = tid; idx < W2_ * HD_; idx += 128) {
        int t = idx >> 5, d = idx & 31;
        size_t off = qbase + (size_t)t * C3 + d;
        qs[t][d] = qkv[off];
        ks[t][d] = qkv[off + C_];
        vs[t][d] = qkv[off + 2 * C_];
    }
    if (tid < W2_) {
        int wh = w >> 2, ww = w & 3;
        int r = wh * WS_ + tid / WS_;
        int c = ww * WS_ + tid % WS_;
        int br = (r < HDIM - WS_) ? 0 : ((r < HDIM - SHIFT_) ? 1 : 2);
        int bc = (c < WDIM - WS_) ? 0 : ((c < WDIM - SHIFT_) ? 1 : 2);
        grp[tid] = br * 3 + bc;
    }
    __syncthreads();

    const float scale = 0.17677669529663687f; // 1/sqrt(32)
    for (int idx = tid; idx < W2_ * W2_; idx += 128) {
        int i = idx / W2_, j = idx - i * W2_;
        float acc = 0.0f;
        #pragma unroll
        for (int d = 0; d < HD_; d++) acc = fmaf(qs[i][d], ks[j][d], acc);
        float bias = rel_table[rel_index[idx] * HEADS_ + head];
        float mask = (grp[i] != grp[j]) ? -100.0f : 0.0f;
        sc[i][j] = acc * scale + bias + mask;
    }
    __syncthreads();

    if (tid < W2_) {
        float mx = -1e30f;
        #pragma unroll 7
        for (int j = 0; j < W2_; j++) mx = fmaxf(mx, sc[tid][j]);
        float sum = 0.0f;
        #pragma unroll 7
        for (int j = 0; j < W2_; j++) {
            float e = __expf(sc[tid][j] - mx);
            sc[tid][j] = e;
            sum += e;
        }
        float inv = 1.0f / sum;
        #pragma unroll 7
        for (int j = 0; j < W2_; j++) sc[tid][j] *= inv;
    }
    __syncthreads();

    const size_t obase = (size_t)win * W2_ * C_ + head * HD_;
    for (int idx = tid; idx < W2_ * HD_; idx += 128) {
        int i = idx >> 5, d = idx & 31;
        float acc = 0.0f;
        #pragma unroll 7
        for (int j = 0; j < W2_; j++) acc = fmaf(sc[i][j], vs[j][d], acc);
        ctx[obase + (size_t)i * C_ + d] = acc;
    }
}

extern "C" void kernel_launch(void* const* d_in, const int* in_sizes, int n_in,
                              void* d_out, int out_size)
{
    const float* x         = (const float*)d_in[0];
    const float* g1        = (const float*)d_in[1];
    const float* b1        = (const float*)d_in[2];
    const float* wq        = (const float*)d_in[3];
    const float* bq        = (const float*)d_in[4];
    const float* wk        = (const float*)d_in[5];
    const float* bk        = (const float*)d_in[6];
    const float* wv        = (const float*)d_in[7];
    const float* bv        = (const float*)d_in[8];
    const float* rel_table = (const float*)d_in[9];
    const float* wo        = (const float*)d_in[10];
    const float* bo        = (const float*)d_in[11];
    const float* g2        = (const float*)d_in[12];
    const float* b2        = (const float*)d_in[13];
    const float* wi        = (const float*)d_in[14];
    const float* bi        = (const float*)d_in[15];
    const float* w_out     = (const float*)d_in[16];
    const float* b_out     = (const float*)d_in[17];
    const int*   rel_index = (const int*)d_in[18];
    float* out = (float*)d_out;

    float *p_win, *p_ctx, *p_x1, *p_h2, *p_mid, *p_wcat, *p_bcat;
    cudaGetSymbolAddress((void**)&p_win,  g_win);
    cudaGetSymbolAddress((void**)&p_ctx,  g_ctx);
    cudaGetSymbolAddress((void**)&p_x1,   g_x1);
    cudaGetSymbolAddress((void**)&p_h2,   g_h2);
    cudaGetSymbolAddress((void**)&p_mid,  g_mid);
    cudaGetSymbolAddress((void**)&p_wcat, g_wcat);
    cudaGetSymbolAddress((void**)&p_bcat, g_bcat);

    cudaFuncSetAttribute(tgemm_kernel,
                         cudaFuncAttributeMaxDynamicSharedMemorySize, SMEM_GEMM);

    // 0. concat qkv weights/biases
    concat_kernel<<<(C_ * C_ + 255) / 256, 256>>>(wq, wk, wv, bq, bk, bv,
                                                  p_wcat, p_bcat);

    // 1. LN1 + cyclic shift + window partition (gather)
    ln_kernel<<<MTOK, 128>>>(x, g1, b1, p_win, 1);

    // 2. fused QKV projection -> g_mid as [MTOK][1536]
    dim3 gQKV(C3 / BN, MTOK / BM);
    tgemm_kernel<<<gQKV, 256, SMEM_GEMM>>>(p_win, p_wcat, p_bcat, p_mid,
                                           MTOK, C3, C_, 0, nullptr);

    // 3. windowed attention (scores + bias + mask + softmax + PV)
    attn_kernel<<<NWIN * HEADS_, 128>>>(p_mid, rel_table, rel_index, p_ctx);

    // 4. output projection + window reverse + un-shift scatter + residual(x)
    dim3 gC(C_ / BN, MTOK / BM);
    tgemm_kernel<<<gC, 256, SMEM_GEMM>>>(p_ctx, wo, bo, p_x1, MTOK, C_, C_, 3, x);

    // 5. LN2
    ln_kernel<<<MTOK, 128>>>(p_x1, g2, b2, p_h2, 0);

    // 6. MLP up-projection + exact GELU
    dim3 gM(MLPD / BN, MTOK / BM);
    tgemm_kernel<<<gM, 256, SMEM_GEMM>>>(p_h2, wi, bi, p_mid, MTOK, MLPD, C_, 1, nullptr);

    // 7. MLP down-projection + residual(x1) -> final output
    tgemm_kernel<<<gC, 256, SMEM_GEMM>>>(p_mid, w_out, b_out, out, MTOK, C_, MLPD, 2, p_x1);
}

// round 9
// speedup vs baseline: 1.1067x; 1.0912x over previous
#include <cuda_runtime.h>
#include <math.h>
#include <stdint.h>

// Problem constants
#define BATCH   64
#define HDIM    28
#define WDIM    28
#define C_      512
#define HEADS_  16
#define WS_     7
#define SHIFT_  3
#define MLPD    2048
#define HD_     32
#define W2_     49
#define NW_     16
#define HW_     784
#define MTOK    50176   // BATCH*HW
#define NWIN    1024    // BATCH*NW
#define C3      1536    // 3*C_ fused qkv width

// Scratch (device globals: no allocation allowed in kernel_launch)
__device__ float g_win[MTOK * C_];
__device__ float g_ctx[MTOK * C_];
__device__ float g_x1[MTOK * C_];
__device__ float g_h2[MTOK * C_];
__device__ float g_mid[(size_t)MTOK * MLPD];   // also holds fused qkv [MTOK][1536]
__device__ float g_wcat[C_ * C3];              // [K=512][N=1536] concat of wq|wk|wv
__device__ float g_bcat[C3];

// Map window-partition row m -> token row in the unshifted [B,H*W] layout.
__device__ __forceinline__ int map_row(int m) {
    int bb  = m / HW_;
    int rem = m - bb * HW_;
    int w   = rem / W2_;
    int t   = rem - w * W2_;
    int wh = w >> 2, ww = w & 3;
    int th = t / WS_, tw = t - th * WS_;
    int r = wh * WS_ + th + SHIFT_; if (r >= HDIM) r -= HDIM;
    int c = ww * WS_ + tw + SHIFT_; if (c >= WDIM) c -= WDIM;
    return bb * HW_ + r * WDIM + c;
}

// Concat qkv weights/biases: wcat[k][j*512+n] = w_j[k][n]
__global__ __launch_bounds__(256) void concat_kernel(
    const float* __restrict__ wq, const float* __restrict__ wk,
    const float* __restrict__ wv, const float* __restrict__ bq,
    const float* __restrict__ bk, const float* __restrict__ bv,
    float* __restrict__ wcat, float* __restrict__ bcat)
{
    int idx = blockIdx.x * 256 + threadIdx.x;
    if (idx < C_ * C_) {
        int k = idx / C_, n = idx - k * C_;
        wcat[(size_t)k * C3 + n        ] = wq[idx];
        wcat[(size_t)k * C3 + n + C_   ] = wk[idx];
        wcat[(size_t)k * C3 + n + 2*C_ ] = wv[idx];
    }
    if (idx < C_) {
        bcat[idx        ] = bq[idx];
        bcat[idx + C_   ] = bk[idx];
        bcat[idx + 2*C_ ] = bv[idx];
    }
}

// LayerNorm over C=512, one block per token row.
__global__ __launch_bounds__(128) void ln_kernel(
    const float* __restrict__ in, const float* __restrict__ g,
    const float* __restrict__ b, float* __restrict__ out, int gather)
{
    int m = blockIdx.x;
    int src = gather ? map_row(m) : m;
    int tid = threadIdx.x;

    float4 xv = ((const float4*)(in + (size_t)src * C_))[tid];
    float s  = xv.x + xv.y + xv.z + xv.w;
    float s2 = xv.x*xv.x + xv.y*xv.y + xv.z*xv.z + xv.w*xv.w;
    #pragma unroll
    for (int off = 16; off; off >>= 1) {
        s  += __shfl_xor_sync(0xffffffffu, s,  off);
        s2 += __shfl_xor_sync(0xffffffffu, s2, off);
    }
    __shared__ float red[8];
    int wid = tid >> 5;
    if ((tid & 31) == 0) { red[wid] = s; red[4 + wid] = s2; }
    __syncthreads();
    s  = red[0] + red[1] + red[2] + red[3];
    s2 = red[4] + red[5] + red[6] + red[7];
    float mu   = s * (1.0f / C_);
    float var  = fmaf(-mu, mu, s2 * (1.0f / C_));
    float rstd = rsqrtf(var + 1e-5f);

    float4 gv = ((const float4*)g)[tid];
    float4 bv = ((const float4*)b)[tid];
    float4 o;
    o.x = (xv.x - mu) * rstd * gv.x + bv.x;
    o.y = (xv.y - mu) * rstd * gv.y + bv.y;
    o.z = (xv.z - mu) * rstd * gv.z + bv.z;
    o.w = (xv.w - mu) * rstd * gv.w + bv.w;
    ((float4*)(out + (size_t)m * C_))[tid] = o;
}

// ---------------------------------------------------------------------------
// TF32 tensor-core GEMM, 5-stage cp.async pipeline, one sync per stage.
// C[M,N] = A[M,K] @ B[K,N] + bias, epilogue modes.
// 256 threads = 8 warps (2 x 4), block tile 128x128, BK=16, warp tile 64x32.
// mode 0: plain   mode 1: exact GELU   mode 2: += res[m]
// mode 3: scatter row via map_row(m), += res[out_row]
// ---------------------------------------------------------------------------
#define BM 128
#define BN 128
#define BKT 16
#define ASTR 20    // As row stride (floats): conflict-free
#define BSTR 136   // Bs row stride (floats): conflict-free
#define NSTAGE 5
#define AFLOATS (BM * ASTR)            // 2560
#define BFLOATS (BKT * BSTR)           // 2176
#define STAGEF  (AFLOATS + BFLOATS)    // 4736 floats = 18944 B
#define SMEM_GEMM (NSTAGE * STAGEF * 4)  // 94720 B

__device__ __forceinline__ void cpa16(uint32_t smem_dst, const void* gsrc) {
    asm volatile("cp.async.cg.shared.global [%0], [%1], 16;\n"
                 :: "r"(smem_dst), "l"(gsrc));
}

__device__ __forceinline__ void mma_tf32(float c[4], uint32_t a0, uint32_t a1,
                                         uint32_t a2, uint32_t a3,
                                         uint32_t b0, uint32_t b1) {
    asm volatile(
        "mma.sync.aligned.m16n8k8.row.col.f32.tf32.tf32.f32 "
        "{%0,%1,%2,%3}, {%4,%5,%6,%7}, {%8,%9}, {%0,%1,%2,%3};"
        : "+f"(c[0]), "+f"(c[1]), "+f"(c[2]), "+f"(c[3])
        : "r"(a0), "r"(a1), "r"(a2), "r"(a3), "r"(b0), "r"(b1));
}

__global__ __launch_bounds__(256) void tgemm_kernel(
    const float* __restrict__ A, const float* __restrict__ Bm,
    const float* __restrict__ bias, float* __restrict__ C,
    int M, int N, int K, int mode, const float* __restrict__ res)
{
    extern __shared__ float sm[];

    const int cRow = blockIdx.y, cCol = blockIdx.x;
    const int tid  = threadIdx.x;
    const int wid  = tid >> 5;
    const int lane = tid & 31;
    const int wm   = wid >> 2;       // 0..1
    const int wn   = wid & 3;        // 0..3
    const int grp  = lane >> 2;      // 0..7
    const int tig  = lane & 3;       // 0..3

    const float* Ab = A  + (size_t)cRow * BM * K;
    const float* Bb = Bm + (size_t)cCol * BN;

    uint32_t smem_base = (uint32_t)__cvta_generic_to_shared(sm);

    float c[4][4][4] = {};

    auto load_tile = [&](int t, int s) {
        const int k0 = t * BKT;
        uint32_t abase = smem_base + (uint32_t)(s * STAGEF * 4);
        uint32_t bbase = abase + AFLOATS * 4;
        #pragma unroll
        for (int cc = 0; cc < 2; cc++) {
            int id = tid * 2 + cc;
            int ar = id >> 2, ak = (id & 3) * 4;
            cpa16(abase + (uint32_t)((ar * ASTR + ak) * 4),
                  Ab + (size_t)ar * K + k0 + ak);
            int br = id >> 5, bn = (id & 31) * 4;
            cpa16(bbase + (uint32_t)((br * BSTR + bn) * 4),
                  Bb + (size_t)(k0 + br) * N + bn);
        }
    };

    const int T = K / BKT;
    #pragma unroll
    for (int s = 0; s < NSTAGE - 1; s++) {
        load_tile(s, s);
        asm volatile("cp.async.commit_group;");
    }

    int ci = 0;            // compute slot
    int pi = NSTAGE - 1;   // prefetch slot
    for (int i = 0; i < T; i++) {
        asm volatile("cp.async.wait_group %0;" :: "n"(NSTAGE - 2));
        __syncthreads();

        if (i + NSTAGE - 1 < T) load_tile(i + NSTAGE - 1, pi);
        asm volatile("cp.async.commit_group;");

        const float* Asb = sm + ci * STAGEF;
        const float* Bsb = Asb + AFLOATS;

        #pragma unroll
        for (int ks = 0; ks < 2; ks++) {
            const int kc = ks * 8 + tig;
            uint32_t a[4][4], b[4][2];
            #pragma unroll
            for (int mi = 0; mi < 4; mi++) {
                int m0 = wm * 64 + mi * 16 + grp;
                a[mi][0] = __float_as_uint(Asb[(m0    ) * ASTR + kc    ]);
                a[mi][1] = __float_as_uint(Asb[(m0 + 8) * ASTR + kc    ]);
                a[mi][2] = __float_as_uint(Asb[(m0    ) * ASTR + kc + 4]);
                a[mi][3] = __float_as_uint(Asb[(m0 + 8) * ASTR + kc + 4]);
            }
            #pragma unroll
            for (int ni = 0; ni < 4; ni++) {
                int n0 = wn * 32 + ni * 8 + grp;
                b[ni][0] = __float_as_uint(Bsb[(ks * 8 + tig    ) * BSTR + n0]);
                b[ni][1] = __float_as_uint(Bsb[(ks * 8 + tig + 4) * BSTR + n0]);
            }
            #pragma unroll
            for (int mi = 0; mi < 4; mi++)
                #pragma unroll
                for (int ni = 0; ni < 4; ni++)
                    mma_tf32(c[mi][ni], a[mi][0], a[mi][1], a[mi][2], a[mi][3],
                             b[ni][0], b[ni][1]);
        }
        ci = (ci + 1 == NSTAGE) ? 0 : ci + 1;
        pi = (pi + 1 == NSTAGE) ? 0 : pi + 1;
    }

    // epilogue
    #pragma unroll
    for (int mi = 0; mi < 4; mi++) {
        #pragma unroll
        for (int rr = 0; rr < 2; rr++) {
            int m = cRow * BM + wm * 64 + mi * 16 + grp + rr * 8;
            int outm = (mode == 3) ? map_row(m) : m;
            #pragma unroll
            for (int ni = 0; ni < 4; ni++) {
                int n = cCol * BN + wn * 32 + ni * 8 + tig * 2;
                float v0 = c[mi][ni][rr * 2 + 0] + bias[n];
                float v1 = c[mi][ni][rr * 2 + 1] + bias[n + 1];
                if (mode == 1) {
                    v0 = 0.5f * v0 * (1.0f + erff(v0 * 0.70710678118654752f));
                    v1 = 0.5f * v1 * (1.0f + erff(v1 * 0.70710678118654752f));
                } else if (mode == 2) {
                    v0 += res[(size_t)m * N + n];
                    v1 += res[(size_t)m * N + n + 1];
                } else if (mode == 3) {
                    v0 += res[(size_t)outm * N + n];
                    v1 += res[(size_t)outm * N + n + 1];
                }
                C[(size_t)outm * N + n]     = v0;
                C[(size_t)outm * N + n + 1] = v1;
            }
        }
    }
}

// ---------------------------------------------------------------------------
// Windowed attention, register-blocked over i (4 rows per smem line).
// One block (128 thr) per (window, head). Reads fused qkv (stride 1536).
// Scores: lane = j, warp accumulates 4 i-rows per ks[j][d] load.
// PV:     lane = d, warp accumulates 4 i-rows per vs[j][d] load.
// ---------------------------------------------------------------------------
#define HDP 33
__global__ __launch_bounds__(128) void attn_kernel(
    const float* __restrict__ qkv, const float* __restrict__ rel_table,
    const int* __restrict__ rel_index, float* __restrict__ ctx)
{
    __shared__ float qs[W2_][HDP];
    __shared__ float ks[W2_][HDP];
    __shared__ float vs[W2_][HDP];
    __shared__ float sc[W2_][W2_ + 1];
    __shared__ int   grp[W2_];

    int blk  = blockIdx.x;
    int head = blk & (HEADS_ - 1);
    int win  = blk >> 4;
    int w    = win & (NW_ - 1);
    int tid  = threadIdx.x;
    int wid  = tid >> 5;
    int lane = tid & 31;

    const size_t qbase = (size_t)win * W2_ * C3 + head * HD_;
    for (int idx = tid; idx < W2_ * HD_; idx += 128) {
        int t = idx >> 5, d = idx & 31;
        size_t off = qbase + (size_t)t * C3 + d;
        qs[t][d] = qkv[off];
        ks[t][d] = qkv[off + C_];
        vs[t][d] = qkv[off + 2 * C_];
    }
    if (tid < W2_) {
        int wh = w >> 2, ww = w & 3;
        int r = wh * WS_ + tid / WS_;
        int c = ww * WS_ + tid % WS_;
        int br = (r < HDIM - WS_) ? 0 : ((r < HDIM - SHIFT_) ? 1 : 2);
        int bc = (c < WDIM - WS_) ? 0 : ((c < WDIM - SHIFT_) ? 1 : 2);
        grp[tid] = br * 3 + bc;
    }
    __syncthreads();

    const float scale = 0.17677669529663687f; // 1/sqrt(32)

    // Scores: 13 i-groups of 4 rows; warps stride over groups; lane = j.
    for (int gi = wid; gi < 13; gi += 4) {
        const int i0 = gi * 4;
        #pragma unroll
        for (int jc = 0; jc < 2; jc++) {
            int j = lane + jc * 32;
            if (j >= W2_) break;
            float acc0 = 0.f, acc1 = 0.f, acc2 = 0.f, acc3 = 0.f;
            #pragma unroll
            for (int d = 0; d < HD_; d++) {
                float kv = ks[j][d];
                acc0 = fmaf(qs[i0][d], kv, acc0);
                if (i0 + 3 < W2_) {
                    acc1 = fmaf(qs[i0 + 1][d], kv, acc1);
                    acc2 = fmaf(qs[i0 + 2][d], kv, acc2);
                    acc3 = fmaf(qs[i0 + 3][d], kv, acc3);
                }
            }
            float accs[4] = {acc0, acc1, acc2, acc3};
            #pragma unroll
            for (int r = 0; r < 4; r++) {
                int i = i0 + r;
                if (i < W2_) {
                    float bias = rel_table[rel_index[i * W2_ + j] * HEADS_ + head];
                    float mask = (grp[i] != grp[j]) ? -100.0f : 0.0f;
                    sc[i][j] = accs[r] * scale + bias + mask;
                }
            }
        }
    }
    __syncthreads();

    // Softmax per row
    if (tid < W2_) {
        float mx = -1e30f;
        #pragma unroll 7
        for (int j = 0; j < W2_; j++) mx = fmaxf(mx, sc[tid][j]);
        float sum = 0.0f;
        #pragma unroll 7
        for (int j = 0; j < W2_; j++) {
            float e = __expf(sc[tid][j] - mx);
            sc[tid][j] = e;
            sum += e;
        }
        float inv = 1.0f / sum;
        #pragma unroll 7
        for (int j = 0; j < W2_; j++) sc[tid][j] *= inv;
    }
    __syncthreads();

    // PV: lane = d, warps stride over i-groups of 4.
    const size_t obase = (size_t)win * W2_ * C_ + head * HD_;
    for (int gi = wid; gi < 13; gi += 4) {
        const int i0 = gi * 4;
        float acc0 = 0.f, acc1 = 0.f, acc2 = 0.f, acc3 = 0.f;
        if (i0 + 3 < W2_) {
            #pragma unroll 7
            for (int j = 0; j < W2_; j++) {
                float vv = vs[j][lane];
                acc0 = fmaf(sc[i0    ][j], vv, acc0);
                acc1 = fmaf(sc[i0 + 1][j], vv, acc1);
                acc2 = fmaf(sc[i0 + 2][j], vv, acc2);
                acc3 = fmaf(sc[i0 + 3][j], vv, acc3);
            }
            ctx[obase + (size_t)(i0    ) * C_ + lane] = acc0;
            ctx[obase + (size_t)(i0 + 1) * C_ + lane] = acc1;
            ctx[obase + (size_t)(i0 + 2) * C_ + lane] = acc2;
            ctx[obase + (size_t)(i0 + 3) * C_ + lane] = acc3;
        } else {
            #pragma unroll 7
            for (int j = 0; j < W2_; j++)
                acc0 = fmaf(sc[i0][j], vs[j][lane], acc0);
            ctx[obase + (size_t)i0 * C_ + lane] = acc0;
        }
    }
}

extern "C" void kernel_launch(void* const* d_in, const int* in_sizes, int n_in,
                              void* d_out, int out_size)
{
    const float* x         = (const float*)d_in[0];
    const float* g1        = (const float*)d_in[1];
    const float* b1        = (const float*)d_in[2];
    const float* wq        = (const float*)d_in[3];
    const float* bq        = (const float*)d_in[4];
    const float* wk        = (const float*)d_in[5];
    const float* bk        = (const float*)d_in[6];
    const float* wv        = (const float*)d_in[7];
    const float* bv        = (const float*)d_in[8];
    const float* rel_table = (const float*)d_in[9];
    const float* wo        = (const float*)d_in[10];
    const float* bo        = (const float*)d_in[11];
    const float* g2        = (const float*)d_in[12];
    const float* b2        = (const float*)d_in[13];
    const float* wi        = (const float*)d_in[14];
    const float* bi        = (const float*)d_in[15];
    const float* w_out     = (const float*)d_in[16];
    const float* b_out     = (const float*)d_in[17];
    const int*   rel_index = (const int*)d_in[18];
    float* out = (float*)d_out;

    float *p_win, *p_ctx, *p_x1, *p_h2, *p_mid, *p_wcat, *p_bcat;
    cudaGetSymbolAddress((void**)&p_win,  g_win);
    cudaGetSymbolAddress((void**)&p_ctx,  g_ctx);
    cudaGetSymbolAddress((void**)&p_x1,   g_x1);
    cudaGetSymbolAddress((void**)&p_h2,   g_h2);
    cudaGetSymbolAddress((void**)&p_mid,  g_mid);
    cudaGetSymbolAddress((void**)&p_wcat, g_wcat);
    cudaGetSymbolAddress((void**)&p_bcat, g_bcat);

    cudaFuncSetAttribute(tgemm_kernel,
                         cudaFuncAttributeMaxDynamicSharedMemorySize, SMEM_GEMM);

    // 0. concat qkv weights/biases
    concat_kernel<<<(C_ * C_ + 255) / 256, 256>>>(wq, wk, wv, bq, bk, bv,
                                                  p_wcat, p_bcat);

    // 1. LN1 + cyclic shift + window partition (gather)
    ln_kernel<<<MTOK, 128>>>(x, g1, b1, p_win, 1);

    // 2. fused QKV projection -> g_mid as [MTOK][1536]
    dim3 gQKV(C3 / BN, MTOK / BM);
    tgemm_kernel<<<gQKV, 256, SMEM_GEMM>>>(p_win, p_wcat, p_bcat, p_mid,
                                           MTOK, C3, C_, 0, nullptr);

    // 3. windowed attention (scores + bias + mask + softmax + PV)
    attn_kernel<<<NWIN * HEADS_, 128>>>(p_mid, rel_table, rel_index, p_ctx);

    // 4. output projection + window reverse + un-shift scatter + residual(x)
    dim3 gC(C_ / BN, MTOK / BM);
    tgemm_kernel<<<gC, 256, SMEM_GEMM>>>(p_ctx, wo, bo, p_x1, MTOK, C_, C_, 3, x);

    // 5. LN2
    ln_kernel<<<MTOK, 128>>>(p_x1, g2, b2, p_h2, 0);

    // 6. MLP up-projection + exact GELU
    dim3 gM(MLPD / BN, MTOK / BM);
    tgemm_kernel<<<gM, 256, SMEM_GEMM>>>(p_h2, wi, bi, p_mid, MTOK, MLPD, C_, 1, nullptr);

    // 7. MLP down-projection + residual(x1) -> final output
    tgemm_kernel<<<gC, 256, SMEM_GEMM>>>(p_mid, w_out, b_out, out, MTOK, C_, MLPD, 2, p_x1);
}

// round 10
// speedup vs baseline: 1.1756x; 1.0622x over previous
#include <cuda_runtime.h>
#include <math.h>
#include <stdint.h>

// Problem constants
#define BATCH   64
#define HDIM    28
#define WDIM    28
#define C_      512
#define HEADS_  16
#define WS_     7
#define SHIFT_  3
#define MLPD    2048
#define HD_     32
#define W2_     49
#define NW_     16
#define HW_     784
#define MTOK    50176   // BATCH*HW
#define NWIN    1024    // BATCH*NW
#define C3      1536    // 3*C_ fused qkv width

// Scratch (device globals: no allocation allowed in kernel_launch)
__device__ float g_win[MTOK * C_];
__device__ float g_ctx[MTOK * C_];
__device__ float g_x1[MTOK * C_];
__device__ float g_h2[MTOK * C_];
__device__ float g_mid[(size_t)MTOK * MLPD];   // also holds fused qkv [MTOK][1536]
__device__ float g_wcat[C_ * C3];              // [K=512][N=1536] concat of wq|wk|wv
__device__ float g_bcat[C3];

// Map window-partition row m -> token row in the unshifted [B,H*W] layout.
__device__ __forceinline__ int map_row(int m) {
    int bb  = m / HW_;
    int rem = m - bb * HW_;
    int w   = rem / W2_;
    int t   = rem - w * W2_;
    int wh = w >> 2, ww = w & 3;
    int th = t / WS_, tw = t - th * WS_;
    int r = wh * WS_ + th + SHIFT_; if (r >= HDIM) r -= HDIM;
    int c = ww * WS_ + tw + SHIFT_; if (c >= WDIM) c -= WDIM;
    return bb * HW_ + r * WDIM + c;
}

// Concat qkv weights/biases: wcat[k][j*512+n] = w_j[k][n]
__global__ __launch_bounds__(256) void concat_kernel(
    const float* __restrict__ wq, const float* __restrict__ wk,
    const float* __restrict__ wv, const float* __restrict__ bq,
    const float* __restrict__ bk, const float* __restrict__ bv,
    float* __restrict__ wcat, float* __restrict__ bcat)
{
    int idx = blockIdx.x * 256 + threadIdx.x;
    if (idx < C_ * C_) {
        int k = idx / C_, n = idx - k * C_;
        wcat[(size_t)k * C3 + n        ] = wq[idx];
        wcat[(size_t)k * C3 + n + C_   ] = wk[idx];
        wcat[(size_t)k * C3 + n + 2*C_ ] = wv[idx];
    }
    if (idx < C_) {
        bcat[idx        ] = bq[idx];
        bcat[idx + C_   ] = bk[idx];
        bcat[idx + 2*C_ ] = bv[idx];
    }
}

// LayerNorm over C=512, one block per token row.
__global__ __launch_bounds__(128) void ln_kernel(
    const float* __restrict__ in, const float* __restrict__ g,
    const float* __restrict__ b, float* __restrict__ out, int gather)
{
    int m = blockIdx.x;
    int src = gather ? map_row(m) : m;
    int tid = threadIdx.x;

    float4 xv = ((const float4*)(in + (size_t)src * C_))[tid];
    float s  = xv.x + xv.y + xv.z + xv.w;
    float s2 = xv.x*xv.x + xv.y*xv.y + xv.z*xv.z + xv.w*xv.w;
    #pragma unroll
    for (int off = 16; off; off >>= 1) {
        s  += __shfl_xor_sync(0xffffffffu, s,  off);
        s2 += __shfl_xor_sync(0xffffffffu, s2, off);
    }
    __shared__ float red[8];
    int wid = tid >> 5;
    if ((tid & 31) == 0) { red[wid] = s; red[4 + wid] = s2; }
    __syncthreads();
    s  = red[0] + red[1] + red[2] + red[3];
    s2 = red[4] + red[5] + red[6] + red[7];
    float mu   = s * (1.0f / C_);
    float var  = fmaf(-mu, mu, s2 * (1.0f / C_));
    float rstd = rsqrtf(var + 1e-5f);

    float4 gv = ((const float4*)g)[tid];
    float4 bv = ((const float4*)b)[tid];
    float4 o;
    o.x = (xv.x - mu) * rstd * gv.x + bv.x;
    o.y = (xv.y - mu) * rstd * gv.y + bv.y;
    o.z = (xv.z - mu) * rstd * gv.z + bv.z;
    o.w = (xv.w - mu) * rstd * gv.w + bv.w;
    ((float4*)(out + (size_t)m * C_))[tid] = o;
}

// ---------------------------------------------------------------------------
// TF32 tensor-core GEMM, 5-stage cp.async pipeline, ldmatrix A-fragments.
// C[M,N] = A[M,K] @ B[K,N] + bias, epilogue modes.
// 256 threads = 8 warps (2 x 4), block tile 128x128, BK=16, warp tile 64x32.
// mode 0: plain   mode 1: exact GELU   mode 2: += res[m]
// mode 3: scatter row via map_row(m), += res[out_row]
// ---------------------------------------------------------------------------
#define BM 128
#define BN 128
#define BKT 16
#define ASTR 20    // As row stride (floats): conflict-free for LDSM phases
#define BSTR 136   // Bs row stride (floats): conflict-free
#define NSTAGE 5
#define AFLOATS (BM * ASTR)            // 2560
#define BFLOATS (BKT * BSTR)           // 2176
#define STAGEF  (AFLOATS + BFLOATS)    // 4736 floats = 18944 B
#define SMEM_GEMM (NSTAGE * STAGEF * 4)  // 94720 B

__device__ __forceinline__ void cpa16(uint32_t smem_dst, const void* gsrc) {
    asm volatile("cp.async.cg.shared.global [%0], [%1], 16;\n"
                 :: "r"(smem_dst), "l"(gsrc));
}

__device__ __forceinline__ void mma_tf32(float c[4], uint32_t a0, uint32_t a1,
                                         uint32_t a2, uint32_t a3,
                                         uint32_t b0, uint32_t b1) {
    asm volatile(
        "mma.sync.aligned.m16n8k8.row.col.f32.tf32.tf32.f32 "
        "{%0,%1,%2,%3}, {%4,%5,%6,%7}, {%8,%9}, {%0,%1,%2,%3};"
        : "+f"(c[0]), "+f"(c[1]), "+f"(c[2]), "+f"(c[3])
        : "r"(a0), "r"(a1), "r"(a2), "r"(a3), "r"(b0), "r"(b1));
}

__device__ __forceinline__ void ldsm4(uint32_t* a, uint32_t addr) {
    asm volatile("ldmatrix.sync.aligned.m8n8.x4.shared.b16 {%0,%1,%2,%3}, [%4];"
                 : "=r"(a[0]), "=r"(a[1]), "=r"(a[2]), "=r"(a[3]) : "r"(addr));
}

__global__ __launch_bounds__(256) void tgemm_kernel(
    const float* __restrict__ A, const float* __restrict__ Bm,
    const float* __restrict__ bias, float* __restrict__ C,
    int M, int N, int K, int mode, const float* __restrict__ res)
{
    extern __shared__ float sm[];

    const int cRow = blockIdx.y, cCol = blockIdx.x;
    const int tid  = threadIdx.x;
    const int wid  = tid >> 5;
    const int lane = tid & 31;
    const int wm   = wid >> 2;       // 0..1
    const int wn   = wid & 3;        // 0..3
    const int grp  = lane >> 2;      // 0..7
    const int tig  = lane & 3;       // 0..3

    // ldmatrix lane address components (x4: m0|m0+8 rows, col +0|+4)
    const int lrow = (lane & 7) + ((lane >> 3) & 1) * 8;  // row within 16
    const int lcol = (lane >> 4) * 4;                     // 0 or 4

    const float* Ab = A  + (size_t)cRow * BM * K;
    const float* Bb = Bm + (size_t)cCol * BN;

    uint32_t smem_base = (uint32_t)__cvta_generic_to_shared(sm);
    // per-thread constant part of ldmatrix address (floats)
    const uint32_t aofs = (uint32_t)(((wm * 64 + lrow) * ASTR + lcol) * 4);

    float c[4][4][4] = {};

    auto load_tile = [&](int t, int s) {
        const int k0 = t * BKT;
        uint32_t abase = smem_base + (uint32_t)(s * STAGEF * 4);
        uint32_t bbase = abase + AFLOATS * 4;
        #pragma unroll
        for (int cc = 0; cc < 2; cc++) {
            int id = tid * 2 + cc;
            int ar = id >> 2, ak = (id & 3) * 4;
            cpa16(abase + (uint32_t)((ar * ASTR + ak) * 4),
                  Ab + (size_t)ar * K + k0 + ak);
            int br = id >> 5, bn = (id & 31) * 4;
            cpa16(bbase + (uint32_t)((br * BSTR + bn) * 4),
                  Bb + (size_t)(k0 + br) * N + bn);
        }
    };

    const int T = K / BKT;
    #pragma unroll
    for (int s = 0; s < NSTAGE - 1; s++) {
        load_tile(s, s);
        asm volatile("cp.async.commit_group;");
    }

    int ci = 0;            // compute slot
    int pi = NSTAGE - 1;   // prefetch slot
    for (int i = 0; i < T; i++) {
        asm volatile("cp.async.wait_group %0;" :: "n"(NSTAGE - 2));
        __syncthreads();

        if (i + NSTAGE - 1 < T) load_tile(i + NSTAGE - 1, pi);
        asm volatile("cp.async.commit_group;");

        const uint32_t aStage = smem_base + (uint32_t)(ci * STAGEF * 4) + aofs;
        const float* Bsb = sm + ci * STAGEF + AFLOATS;

        #pragma unroll
        for (int ks = 0; ks < 2; ks++) {
            uint32_t a[4][4], b[4][2];
            #pragma unroll
            for (int mi = 0; mi < 4; mi++)
                ldsm4(a[mi], aStage + (uint32_t)(mi * 16 * ASTR * 4 + ks * 32));
            #pragma unroll
            for (int ni = 0; ni < 4; ni++) {
                int n0 = wn * 32 + ni * 8 + grp;
                b[ni][0] = __float_as_uint(Bsb[(ks * 8 + tig    ) * BSTR + n0]);
                b[ni][1] = __float_as_uint(Bsb[(ks * 8 + tig + 4) * BSTR + n0]);
            }
            #pragma unroll
            for (int mi = 0; mi < 4; mi++)
                #pragma unroll
                for (int ni = 0; ni < 4; ni++)
                    mma_tf32(c[mi][ni], a[mi][0], a[mi][1], a[mi][2], a[mi][3],
                             b[ni][0], b[ni][1]);
        }
        ci = (ci + 1 == NSTAGE) ? 0 : ci + 1;
        pi = (pi + 1 == NSTAGE) ? 0 : pi + 1;
    }

    // epilogue
    #pragma unroll
    for (int mi = 0; mi < 4; mi++) {
        #pragma unroll
        for (int rr = 0; rr < 2; rr++) {
            int m = cRow * BM + wm * 64 + mi * 16 + grp + rr * 8;
            int outm = (mode == 3) ? map_row(m) : m;
            #pragma unroll
            for (int ni = 0; ni < 4; ni++) {
                int n = cCol * BN + wn * 32 + ni * 8 + tig * 2;
                float v0 = c[mi][ni][rr * 2 + 0] + bias[n];
                float v1 = c[mi][ni][rr * 2 + 1] + bias[n + 1];
                if (mode == 1) {
                    v0 = 0.5f * v0 * (1.0f + erff(v0 * 0.70710678118654752f));
                    v1 = 0.5f * v1 * (1.0f + erff(v1 * 0.70710678118654752f));
                } else if (mode == 2) {
                    v0 += res[(size_t)m * N + n];
                    v1 += res[(size_t)m * N + n + 1];
                } else if (mode == 3) {
                    v0 += res[(size_t)outm * N + n];
                    v1 += res[(size_t)outm * N + n + 1];
                }
                C[(size_t)outm * N + n]     = v0;
                C[(size_t)outm * N + n + 1] = v1;
            }
        }
    }
}

// ---------------------------------------------------------------------------
// Windowed attention, float4-vectorized, register-blocked over i (4 rows).
// One block (128 thr) per (window, head). Reads fused qkv (stride 1536).
// q/k/v tiles stored as float4[W2][9] (row stride 36 floats; conflict-free
// for both float4 row reads and scalar column reads).
// ---------------------------------------------------------------------------
#define HDP4 9     // float4 per row (36 floats)
#define SCS 52     // sc row stride (floats), 16B-aligned rows
__global__ __launch_bounds__(128) void attn_kernel(
    const float* __restrict__ qkv, const float* __restrict__ rel_table,
    const int* __restrict__ rel_index, float* __restrict__ ctx)
{
    __shared__ float4 qs4[W2_][HDP4];
    __shared__ float4 ks4[W2_][HDP4];
    __shared__ float4 vs4[W2_][HDP4];
    __shared__ float  sc[W2_][SCS];
    __shared__ int    grp[W2_];

    int blk  = blockIdx.x;
    int head = blk & (HEADS_ - 1);
    int win  = blk >> 4;
    int w    = win & (NW_ - 1);
    int tid  = threadIdx.x;
    int wid  = tid >> 5;
    int lane = tid & 31;

    const size_t qbase = (size_t)win * W2_ * C3 + head * HD_;
    for (int idx = tid; idx < W2_ * 8; idx += 128) {
        int t = idx >> 3, dc = idx & 7;
        const float* p = qkv + qbase + (size_t)t * C3 + dc * 4;
        qs4[t][dc] = *(const float4*)(p);
        ks4[t][dc] = *(const float4*)(p + C_);
        vs4[t][dc] = *(const float4*)(p + 2 * C_);
    }
    if (tid < W2_) {
        int wh = w >> 2, ww = w & 3;
        int r = wh * WS_ + tid / WS_;
        int c = ww * WS_ + tid % WS_;
        int br = (r < HDIM - WS_) ? 0 : ((r < HDIM - SHIFT_) ? 1 : 2);
        int bc = (c < WDIM - WS_) ? 0 : ((c < WDIM - SHIFT_) ? 1 : 2);
        grp[tid] = br * 3 + bc;
    }
    __syncthreads();

    const float scale = 0.17677669529663687f; // 1/sqrt(32)

    // Scores: 13 i-groups of 4 rows; warps stride over groups; lane = j.
    for (int gi = wid; gi < 13; gi += 4) {
        const int i0 = gi * 4;
        const bool full = (i0 + 3 < W2_);
        #pragma unroll
        for (int jc = 0; jc < 2; jc++) {
            int j = lane + jc * 32;
            if (j >= W2_) break;
            float a0 = 0.f, a1 = 0.f, a2 = 0.f, a3 = 0.f;
            #pragma unroll
            for (int dc = 0; dc < 8; dc++) {
                float4 kv = ks4[j][dc];
                float4 q0 = qs4[i0][dc];
                a0 += q0.x*kv.x + q0.y*kv.y + q0.z*kv.z + q0.w*kv.w;
                if (full) {
                    float4 q1 = qs4[i0 + 1][dc];
                    float4 q2 = qs4[i0 + 2][dc];
                    float4 q3 = qs4[i0 + 3][dc];
                    a1 += q1.x*kv.x + q1.y*kv.y + q1.z*kv.z + q1.w*kv.w;
                    a2 += q2.x*kv.x + q2.y*kv.y + q2.z*kv.z + q2.w*kv.w;
                    a3 += q3.x*kv.x + q3.y*kv.y + q3.z*kv.z + q3.w*kv.w;
                }
            }
            float accs[4] = {a0, a1, a2, a3};
            int nr = full ? 4 : 1;
            for (int r = 0; r < nr; r++) {
                int i = i0 + r;
                float bias = rel_table[rel_index[i * W2_ + j] * HEADS_ + head];
                float mask = (grp[i] != grp[j]) ? -100.0f : 0.0f;
                sc[i][j] = accs[r] * scale + bias + mask;
            }
        }
    }
    __syncthreads();

    // Softmax per row
    if (tid < W2_) {
        float mx = -1e30f;
        #pragma unroll 7
        for (int j = 0; j < W2_; j++) mx = fmaxf(mx, sc[tid][j]);
        float sum = 0.0f;
        #pragma unroll 7
        for (int j = 0; j < W2_; j++) {
            float e = __expf(sc[tid][j] - mx);
            sc[tid][j] = e;
            sum += e;
        }
        float inv = 1.0f / sum;
        #pragma unroll 7
        for (int j = 0; j < W2_; j++) sc[tid][j] *= inv;
    }
    __syncthreads();

    // PV: lane = d, warps stride over i-groups of 4; probs read as float4.
    const float* vsf = (const float*)vs4;   // vs[j][d] = vsf[j*36 + d]
    const size_t obase = (size_t)win * W2_ * C_ + head * HD_;
    for (int gi = wid; gi < 13; gi += 4) {
        const int i0 = gi * 4;
        float a0 = 0.f, a1 = 0.f, a2 = 0.f, a3 = 0.f;
        if (i0 + 3 < W2_) {
            #pragma unroll
            for (int jc = 0; jc < 12; jc++) {
                int j = jc * 4;
                float v0 = vsf[(j    ) * 36 + lane];
                float v1 = vsf[(j + 1) * 36 + lane];
                float v2 = vsf[(j + 2) * 36 + lane];
                float v3 = vsf[(j + 3) * 36 + lane];
                float4 p0 = *(const float4*)&sc[i0    ][j];
                float4 p1 = *(const float4*)&sc[i0 + 1][j];
                float4 p2 = *(const float4*)&sc[i0 + 2][j];
                float4 p3 = *(const float4*)&sc[i0 + 3][j];
                a0 += p0.x*v0 + p0.y*v1 + p0.z*v2 + p0.w*v3;
                a1 += p1.x*v0 + p1.y*v1 + p1.z*v2 + p1.w*v3;
                a2 += p2.x*v0 + p2.y*v1 + p2.z*v2 + p2.w*v3;
                a3 += p3.x*v0 + p3.y*v1 + p3.z*v2 + p3.w*v3;
            }
            {   // tail j = 48
                float v = vsf[48 * 36 + lane];
                a0 += sc[i0    ][48] * v;
                a1 += sc[i0 + 1][48] * v;
                a2 += sc[i0 + 2][48] * v;
                a3 += sc[i0 + 3][48] * v;
            }
            ctx[obase + (size_t)(i0    ) * C_ + lane] = a0;
            ctx[obase + (size_t)(i0 + 1) * C_ + lane] = a1;
            ctx[obase + (size_t)(i0 + 2) * C_ + lane] = a2;
            ctx[obase + (size_t)(i0 + 3) * C_ + lane] = a3;
        } else {
            #pragma unroll 7
            for (int j = 0; j < W2_; j++)
                a0 += sc[i0][j] * vsf[j * 36 + lane];
            ctx[obase + (size_t)i0 * C_ + lane] = a0;
        }
    }
}

extern "C" void kernel_launch(void* const* d_in, const int* in_sizes, int n_in,
                              void* d_out, int out_size)
{
    const float* x         = (const float*)d_in[0];
    const float* g1        = (const float*)d_in[1];
    const float* b1        = (const float*)d_in[2];
    const float* wq        = (const float*)d_in[3];
    const float* bq        = (const float*)d_in[4];
    const float* wk        = (const float*)d_in[5];
    const float* bk        = (const float*)d_in[6];
    const float* wv        = (const float*)d_in[7];
    const float* bv        = (const float*)d_in[8];
    const float* rel_table = (const float*)d_in[9];
    const float* wo        = (const float*)d_in[10];
    const float* bo        = (const float*)d_in[11];
    const float* g2        = (const float*)d_in[12];
    const float* b2        = (const float*)d_in[13];
    const float* wi        = (const float*)d_in[14];
    const float* bi        = (const float*)d_in[15];
    const float* w_out     = (const float*)d_in[16];
    const float* b_out     = (const float*)d_in[17];
    const int*   rel_index = (const int*)d_in[18];
    float* out = (float*)d_out;

    float *p_win, *p_ctx, *p_x1, *p_h2, *p_mid, *p_wcat, *p_bcat;
    cudaGetSymbolAddress((void**)&p_win,  g_win);
    cudaGetSymbolAddress((void**)&p_ctx,  g_ctx);
    cudaGetSymbolAddress((void**)&p_x1,   g_x1);
    cudaGetSymbolAddress((void**)&p_h2,   g_h2);
    cudaGetSymbolAddress((void**)&p_mid,  g_mid);
    cudaGetSymbolAddress((void**)&p_wcat, g_wcat);
    cudaGetSymbolAddress((void**)&p_bcat, g_bcat);

    cudaFuncSetAttribute(tgemm_kernel,
                         cudaFuncAttributeMaxDynamicSharedMemorySize, SMEM_GEMM);

    // 0. concat qkv weights/biases
    concat_kernel<<<(C_ * C_ + 255) / 256, 256>>>(wq, wk, wv, bq, bk, bv,
                                                  p_wcat, p_bcat);

    // 1. LN1 + cyclic shift + window partition (gather)
    ln_kernel<<<MTOK, 128>>>(x, g1, b1, p_win, 1);

    // 2. fused QKV projection -> g_mid as [MTOK][1536]
    dim3 gQKV(C3 / BN, MTOK / BM);
    tgemm_kernel<<<gQKV, 256, SMEM_GEMM>>>(p_win, p_wcat, p_bcat, p_mid,
                                           MTOK, C3, C_, 0, nullptr);

    // 3. windowed attention (scores + bias + mask + softmax + PV)
    attn_kernel<<<NWIN * HEADS_, 128>>>(p_mid, rel_table, rel_index, p_ctx);

    // 4. output projection + window reverse + un-shift scatter + residual(x)
    dim3 gC(C_ / BN, MTOK / BM);
    tgemm_kernel<<<gC, 256, SMEM_GEMM>>>(p_ctx, wo, bo, p_x1, MTOK, C_, C_, 3, x);

    // 5. LN2
    ln_kernel<<<MTOK, 128>>>(p_x1, g2, b2, p_h2, 0);

    // 6. MLP up-projection + exact GELU
    dim3 gM(MLPD / BN, MTOK / BM);
    tgemm_kernel<<<gM, 256, SMEM_GEMM>>>(p_h2, wi, bi, p_mid, MTOK, MLPD, C_, 1, nullptr);

    // 7. MLP down-projection + residual(x1) -> final output
    tgemm_kernel<<<gC, 256, SMEM_GEMM>>>(p_mid, w_out, b_out, out, MTOK, C_, MLPD, 2, p_x1);
}

// round 11
// speedup vs baseline: 1.2425x; 1.0569x over previous
#include <cuda_runtime.h>
#include <math.h>
#include <stdint.h>

// Problem constants
#define BATCH   64
#define HDIM    28
#define WDIM    28
#define C_      512
#define HEADS_  16
#define WS_     7
#define SHIFT_  3
#define MLPD    2048
#define HD_     32
#define W2_     49
#define NW_     16
#define HW_     784
#define MTOK    50176   // BATCH*HW
#define NWIN    1024    // BATCH*NW
#define C3      1536    // 3*C_ fused qkv width

// Scratch (device globals: no allocation allowed in kernel_launch)
__device__ float g_win[MTOK * C_];
__device__ float g_ctx[MTOK * C_];
__device__ float g_x1[MTOK * C_];
__device__ float g_h2[MTOK * C_];
__device__ float g_mid[(size_t)MTOK * MLPD];   // also holds fused qkv [MTOK][1536]
__device__ float g_bcat[C3];
// Transposed (K-major, [N][K]) weights: qkvT | woT | wiT | woutT
#define WT_QKV 0
#define WT_O   (C3 * C_)
#define WT_I   (WT_O + C_ * C_)
#define WT_OUT (WT_I + MLPD * C_)
__device__ float g_wT[WT_OUT + C_ * MLPD];

// Map window-partition row m -> token row in the unshifted [B,H*W] layout.
__device__ __forceinline__ int map_row(int m) {
    int bb  = m / HW_;
    int rem = m - bb * HW_;
    int w   = rem / W2_;
    int t   = rem - w * W2_;
    int wh = w >> 2, ww = w & 3;
    int th = t / WS_, tw = t - th * WS_;
    int r = wh * WS_ + th + SHIFT_; if (r >= HDIM) r -= HDIM;
    int c = ww * WS_ + tw + SHIFT_; if (c >= WDIM) c -= WDIM;
    return bb * HW_ + r * WDIM + c;
}

// Tiled transpose: out[Cc][R] = in[R][Cc]^T. Dims multiples of 32.
__global__ __launch_bounds__(256) void transpose_kernel(
    const float* __restrict__ in, float* __restrict__ out, int R, int Cc)
{
    __shared__ float t[32][33];
    int bx = blockIdx.x * 32, by = blockIdx.y * 32;
    int tx = threadIdx.x & 31, ty = threadIdx.x >> 5;
    #pragma unroll
    for (int j = 0; j < 32; j += 8)
        t[ty + j][tx] = in[(size_t)(by + ty + j) * Cc + bx + tx];
    __syncthreads();
    #pragma unroll
    for (int j = 0; j < 32; j += 8)
        out[(size_t)(bx + ty + j) * R + by + tx] = t[tx][ty + j];
}

// Concat qkv biases
__global__ __launch_bounds__(256) void bcat_kernel(
    const float* __restrict__ bq, const float* __restrict__ bk,
    const float* __restrict__ bv, float* __restrict__ bcat)
{
    int idx = blockIdx.x * 256 + threadIdx.x;
    if (idx < C_) {
        bcat[idx        ] = bq[idx];
        bcat[idx + C_   ] = bk[idx];
        bcat[idx + 2*C_ ] = bv[idx];
    }
}

// LayerNorm over C=512, one block per token row.
__global__ __launch_bounds__(128) void ln_kernel(
    const float* __restrict__ in, const float* __restrict__ g,
    const float* __restrict__ b, float* __restrict__ out, int gather)
{
    int m = blockIdx.x;
    int src = gather ? map_row(m) : m;
    int tid = threadIdx.x;

    float4 xv = ((const float4*)(in + (size_t)src * C_))[tid];
    float s  = xv.x + xv.y + xv.z + xv.w;
    float s2 = xv.x*xv.x + xv.y*xv.y + xv.z*xv.z + xv.w*xv.w;
    #pragma unroll
    for (int off = 16; off; off >>= 1) {
        s  += __shfl_xor_sync(0xffffffffu, s,  off);
        s2 += __shfl_xor_sync(0xffffffffu, s2, off);
    }
    __shared__ float red[8];
    int wid = tid >> 5;
    if ((tid & 31) == 0) { red[wid] = s; red[4 + wid] = s2; }
    __syncthreads();
    s  = red[0] + red[1] + red[2] + red[3];
    s2 = red[4] + red[5] + red[6] + red[7];
    float mu   = s * (1.0f / C_);
    float var  = fmaf(-mu, mu, s2 * (1.0f / C_));
    float rstd = rsqrtf(var + 1e-5f);

    float4 gv = ((const float4*)g)[tid];
    float4 bv = ((const float4*)b)[tid];
    float4 o;
    o.x = (xv.x - mu) * rstd * gv.x + bv.x;
    o.y = (xv.y - mu) * rstd * gv.y + bv.y;
    o.z = (xv.z - mu) * rstd * gv.z + bv.z;
    o.w = (xv.w - mu) * rstd * gv.w + bv.w;
    ((float4*)(out + (size_t)m * C_))[tid] = o;
}

// ---------------------------------------------------------------------------
// TF32 tensor-core GEMM, 5-stage cp.async pipeline, ldmatrix A AND B frags.
// C[M,N] = A[M,K] @ Bt[N,K]^T + bias, epilogue modes.
// Both operands K-major in smem, identical layout (stride ASTR).
// 256 threads = 8 warps (2 x 4), block tile 128x128, BK=16, warp tile 64x32.
// mode 0: plain   mode 1: exact GELU   mode 2: += res[m]
// mode 3: scatter row via map_row(m), += res[out_row]
// ---------------------------------------------------------------------------
#define BM 128
#define BN 128
#define BKT 16
#define ASTR 20    // row stride (floats): conflict-free for LDSM phases
#define NSTAGE 5
#define AFLOATS (BM * ASTR)            // 2560
#define STAGEF  (2 * AFLOATS)          // 5120 floats = 20480 B
#define SMEM_GEMM (NSTAGE * STAGEF * 4)  // 102400 B

__device__ __forceinline__ void cpa16(uint32_t smem_dst, const void* gsrc) {
    asm volatile("cp.async.cg.shared.global [%0], [%1], 16;\n"
                 :: "r"(smem_dst), "l"(gsrc));
}

__device__ __forceinline__ void mma_tf32(float c[4], uint32_t a0, uint32_t a1,
                                         uint32_t a2, uint32_t a3,
                                         uint32_t b0, uint32_t b1) {
    asm volatile(
        "mma.sync.aligned.m16n8k8.row.col.f32.tf32.tf32.f32 "
        "{%0,%1,%2,%3}, {%4,%5,%6,%7}, {%8,%9}, {%0,%1,%2,%3};"
        : "+f"(c[0]), "+f"(c[1]), "+f"(c[2]), "+f"(c[3])
        : "r"(a0), "r"(a1), "r"(a2), "r"(a3), "r"(b0), "r"(b1));
}

__device__ __forceinline__ void ldsm4(uint32_t* a, uint32_t addr) {
    asm volatile("ldmatrix.sync.aligned.m8n8.x4.shared.b16 {%0,%1,%2,%3}, [%4];"
                 : "=r"(a[0]), "=r"(a[1]), "=r"(a[2]), "=r"(a[3]) : "r"(addr));
}

__global__ __launch_bounds__(256) void tgemm_kernel(
    const float* __restrict__ A, const float* __restrict__ Bt,
    const float* __restrict__ bias, float* __restrict__ C,
    int M, int N, int K, int mode, const float* __restrict__ res)
{
    extern __shared__ float sm[];

    const int cRow = blockIdx.y, cCol = blockIdx.x;
    const int tid  = threadIdx.x;
    const int wid  = tid >> 5;
    const int lane = tid & 31;
    const int wm   = wid >> 2;       // 0..1
    const int wn   = wid & 3;        // 0..3
    const int grp  = lane >> 2;      // 0..7
    const int tig  = lane & 3;       // 0..3

    // ldmatrix lane address components
    const int lrowA = (lane & 7) + ((lane >> 3) & 1) * 8;  // A: row within 16
    const int lcolA = (lane >> 4) * 4;                     // A: col 0 or 4
    const int lrowB = (lane & 7) + (lane >> 4) * 8;        // B: n within 16
    const int lcolB = ((lane >> 3) & 1) * 4;               // B: col 0 or 4

    const float* Ab = A  + (size_t)cRow * BM * K;
    const float* Bb = Bt + (size_t)cCol * BN * K;

    uint32_t smem_base = (uint32_t)__cvta_generic_to_shared(sm);
    const uint32_t aofs = (uint32_t)(((wm * 64 + lrowA) * ASTR + lcolA) * 4);
    const uint32_t bofs = (uint32_t)(AFLOATS * 4) +
                          (uint32_t)(((wn * 32 + lrowB) * ASTR + lcolB) * 4);

    float c[4][4][4] = {};

    // Both tiles 128 rows x 16 k-floats, same cp.async mapping.
    auto load_tile = [&](int t, int s) {
        const int k0 = t * BKT;
        uint32_t abase = smem_base + (uint32_t)(s * STAGEF * 4);
        uint32_t bbase = abase + AFLOATS * 4;
        #pragma unroll
        for (int cc = 0; cc < 2; cc++) {
            int id = tid * 2 + cc;
            int r = id >> 2, kk = (id & 3) * 4;
            cpa16(abase + (uint32_t)((r * ASTR + kk) * 4),
                  Ab + (size_t)r * K + k0 + kk);
            cpa16(bbase + (uint32_t)((r * ASTR + kk) * 4),
                  Bb + (size_t)r * K + k0 + kk);
        }
    };

    const int T = K / BKT;
    #pragma unroll
    for (int s = 0; s < NSTAGE - 1; s++) {
        load_tile(s, s);
        asm volatile("cp.async.commit_group;");
    }

    int ci = 0;            // compute slot
    int pi = NSTAGE - 1;   // prefetch slot
    for (int i = 0; i < T; i++) {
        asm volatile("cp.async.wait_group %0;" :: "n"(NSTAGE - 2));
        __syncthreads();

        if (i + NSTAGE - 1 < T) load_tile(i + NSTAGE - 1, pi);
        asm volatile("cp.async.commit_group;");

        const uint32_t stage = smem_base + (uint32_t)(ci * STAGEF * 4);
        const uint32_t aStage = stage + aofs;
        const uint32_t bStage = stage + bofs;

        #pragma unroll
        for (int ks = 0; ks < 2; ks++) {
            uint32_t a[4][4], b[4][2];
            #pragma unroll
            for (int mi = 0; mi < 4; mi++)
                ldsm4(a[mi], aStage + (uint32_t)(mi * 16 * ASTR * 4 + ks * 32));
            #pragma unroll
            for (int p = 0; p < 2; p++) {
                uint32_t t4[4];
                ldsm4(t4, bStage + (uint32_t)(p * 16 * ASTR * 4 + ks * 32));
                b[p*2    ][0] = t4[0];
                b[p*2    ][1] = t4[1];
                b[p*2 + 1][0] = t4[2];
                b[p*2 + 1][1] = t4[3];
            }
            #pragma unroll
            for (int mi = 0; mi < 4; mi++)
                #pragma unroll
                for (int ni = 0; ni < 4; ni++)
                    mma_tf32(c[mi][ni], a[mi][0], a[mi][1], a[mi][2], a[mi][3],
                             b[ni][0], b[ni][1]);
        }
        ci = (ci + 1 == NSTAGE) ? 0 : ci + 1;
        pi = (pi + 1 == NSTAGE) ? 0 : pi + 1;
    }

    // epilogue
    #pragma unroll
    for (int mi = 0; mi < 4; mi++) {
        #pragma unroll
        for (int rr = 0; rr < 2; rr++) {
            int m = cRow * BM + wm * 64 + mi * 16 + grp + rr * 8;
            int outm = (mode == 3) ? map_row(m) : m;
            #pragma unroll
            for (int ni = 0; ni < 4; ni++) {
                int n = cCol * BN + wn * 32 + ni * 8 + tig * 2;
                float v0 = c[mi][ni][rr * 2 + 0] + bias[n];
                float v1 = c[mi][ni][rr * 2 + 1] + bias[n + 1];
                if (mode == 1) {
                    v0 = 0.5f * v0 * (1.0f + erff(v0 * 0.70710678118654752f));
                    v1 = 0.5f * v1 * (1.0f + erff(v1 * 0.70710678118654752f));
                } else if (mode == 2) {
                    v0 += res[(size_t)m * N + n];
                    v1 += res[(size_t)m * N + n + 1];
                } else if (mode == 3) {
                    v0 += res[(size_t)outm * N + n];
                    v1 += res[(size_t)outm * N + n + 1];
                }
                C[(size_t)outm * N + n]     = v0;
                C[(size_t)outm * N + n + 1] = v1;
            }
        }
    }
}

// ---------------------------------------------------------------------------
// Windowed attention, float4-vectorized, register-blocked over i (4 rows).
// One block (128 thr) per (window, head). Reads fused qkv (stride 1536).
// ---------------------------------------------------------------------------
#define HDP4 9     // float4 per row (36 floats)
#define SCS 52     // sc row stride (floats), 16B-aligned rows
__global__ __launch_bounds__(128) void attn_kernel(
    const float* __restrict__ qkv, const float* __restrict__ rel_table,
    const int* __restrict__ rel_index, float* __restrict__ ctx)
{
    __shared__ float4 qs4[W2_][HDP4];
    __shared__ float4 ks4[W2_][HDP4];
    __shared__ float4 vs4[W2_][HDP4];
    __shared__ float  sc[W2_][SCS];
    __shared__ int    grp[W2_];

    int blk  = blockIdx.x;
    int head = blk & (HEADS_ - 1);
    int win  = blk >> 4;
    int w    = win & (NW_ - 1);
    int tid  = threadIdx.x;
    int wid  = tid >> 5;
    int lane = tid & 31;

    const size_t qbase = (size_t)win * W2_ * C3 + head * HD_;
    for (int idx = tid; idx < W2_ * 8; idx += 128) {
        int t = idx >> 3, dc = idx & 7;
        const float* p = qkv + qbase + (size_t)t * C3 + dc * 4;
        qs4[t][dc] = *(const float4*)(p);
        ks4[t][dc] = *(const float4*)(p + C_);
        vs4[t][dc] = *(const float4*)(p + 2 * C_);
    }
    if (tid < W2_) {
        int wh = w >> 2, ww = w & 3;
        int r = wh * WS_ + tid / WS_;
        int c = ww * WS_ + tid % WS_;
        int br = (r < HDIM - WS_) ? 0 : ((r < HDIM - SHIFT_) ? 1 : 2);
        int bc = (c < WDIM - WS_) ? 0 : ((c < WDIM - SHIFT_) ? 1 : 2);
        grp[tid] = br * 3 + bc;
    }
    __syncthreads();

    const float scale = 0.17677669529663687f; // 1/sqrt(32)

    // Scores: 13 i-groups of 4 rows; warps stride over groups; lane = j.
    for (int gi = wid; gi < 13; gi += 4) {
        const int i0 = gi * 4;
        const bool full = (i0 + 3 < W2_);
        #pragma unroll
        for (int jc = 0; jc < 2; jc++) {
            int j = lane + jc * 32;
            if (j >= W2_) break;
            float a0 = 0.f, a1 = 0.f, a2 = 0.f, a3 = 0.f;
            #pragma unroll
            for (int dc = 0; dc < 8; dc++) {
                float4 kv = ks4[j][dc];
                float4 q0 = qs4[i0][dc];
                a0 += q0.x*kv.x + q0.y*kv.y + q0.z*kv.z + q0.w*kv.w;
                if (full) {
                    float4 q1 = qs4[i0 + 1][dc];
                    float4 q2 = qs4[i0 + 2][dc];
                    float4 q3 = qs4[i0 + 3][dc];
                    a1 += q1.x*kv.x + q1.y*kv.y + q1.z*kv.z + q1.w*kv.w;
                    a2 += q2.x*kv.x + q2.y*kv.y + q2.z*kv.z + q2.w*kv.w;
                    a3 += q3.x*kv.x + q3.y*kv.y + q3.z*kv.z + q3.w*kv.w;
                }
            }
            float accs[4] = {a0, a1, a2, a3};
            int nr = full ? 4 : 1;
            for (int r = 0; r < nr; r++) {
                int i = i0 + r;
                float bias = rel_table[rel_index[i * W2_ + j] * HEADS_ + head];
                float mask = (grp[i] != grp[j]) ? -100.0f : 0.0f;
                sc[i][j] = accs[r] * scale + bias + mask;
            }
        }
    }
    __syncthreads();

    // Softmax per row
    if (tid < W2_) {
        float mx = -1e30f;
        #pragma unroll 7
        for (int j = 0; j < W2_; j++) mx = fmaxf(mx, sc[tid][j]);
        float sum = 0.0f;
        #pragma unroll 7
        for (int j = 0; j < W2_; j++) {
            float e = __expf(sc[tid][j] - mx);
            sc[tid][j] = e;
            sum += e;
        }
        float inv = 1.0f / sum;
        #pragma unroll 7
        for (int j = 0; j < W2_; j++) sc[tid][j] *= inv;
    }
    __syncthreads();

    // PV: lane = d, warps stride over i-groups of 4; probs read as float4.
    const float* vsf = (const float*)vs4;   // vs[j][d] = vsf[j*36 + d]
    const size_t obase = (size_t)win * W2_ * C_ + head * HD_;
    for (int gi = wid; gi < 13; gi += 4) {
        const int i0 = gi * 4;
        float a0 = 0.f, a1 = 0.f, a2 = 0.f, a3 = 0.f;
        if (i0 + 3 < W2_) {
            #pragma unroll
            for (int jc = 0; jc < 12; jc++) {
                int j = jc * 4;
                float v0 = vsf[(j    ) * 36 + lane];
                float v1 = vsf[(j + 1) * 36 + lane];
                float v2 = vsf[(j + 2) * 36 + lane];
                float v3 = vsf[(j + 3) * 36 + lane];
                float4 p0 = *(const float4*)&sc[i0    ][j];
                float4 p1 = *(const float4*)&sc[i0 + 1][j];
                float4 p2 = *(const float4*)&sc[i0 + 2][j];
                float4 p3 = *(const float4*)&sc[i0 + 3][j];
                a0 += p0.x*v0 + p0.y*v1 + p0.z*v2 + p0.w*v3;
                a1 += p1.x*v0 + p1.y*v1 + p1.z*v2 + p1.w*v3;
                a2 += p2.x*v0 + p2.y*v1 + p2.z*v2 + p2.w*v3;
                a3 += p3.x*v0 + p3.y*v1 + p3.z*v2 + p3.w*v3;
            }
            {   // tail j = 48
                float v = vsf[48 * 36 + lane];
                a0 += sc[i0    ][48] * v;
                a1 += sc[i0 + 1][48] * v;
                a2 += sc[i0 + 2][48] * v;
                a3 += sc[i0 + 3][48] * v;
            }
            ctx[obase + (size_t)(i0    ) * C_ + lane] = a0;
            ctx[obase + (size_t)(i0 + 1) * C_ + lane] = a1;
            ctx[obase + (size_t)(i0 + 2) * C_ + lane] = a2;
            ctx[obase + (size_t)(i0 + 3) * C_ + lane] = a3;
        } else {
            #pragma unroll 7
            for (int j = 0; j < W2_; j++)
                a0 += sc[i0][j] * vsf[j * 36 + lane];
            ctx[obase + (size_t)i0 * C_ + lane] = a0;
        }
    }
}

extern "C" void kernel_launch(void* const* d_in, const int* in_sizes, int n_in,
                              void* d_out, int out_size)
{
    const float* x         = (const float*)d_in[0];
    const float* g1        = (const float*)d_in[1];
    const float* b1        = (const float*)d_in[2];
    const float* wq        = (const float*)d_in[3];
    const float* bq        = (const float*)d_in[4];
    const float* wk        = (const float*)d_in[5];
    const float* bk        = (const float*)d_in[6];
    const float* wv        = (const float*)d_in[7];
    const float* bv        = (const float*)d_in[8];
    const float* rel_table = (const float*)d_in[9];
    const float* wo        = (const float*)d_in[10];
    const float* bo        = (const float*)d_in[11];
    const float* g2        = (const float*)d_in[12];
    const float* b2        = (const float*)d_in[13];
    const float* wi        = (const float*)d_in[14];
    const float* bi        = (const float*)d_in[15];
    const float* w_out     = (const float*)d_in[16];
    const float* b_out     = (const float*)d_in[17];
    const int*   rel_index = (const int*)d_in[18];
    float* out = (float*)d_out;

    float *p_win, *p_ctx, *p_x1, *p_h2, *p_mid, *p_bcat, *p_wT;
    cudaGetSymbolAddress((void**)&p_win,  g_win);
    cudaGetSymbolAddress((void**)&p_ctx,  g_ctx);
    cudaGetSymbolAddress((void**)&p_x1,   g_x1);
    cudaGetSymbolAddress((void**)&p_h2,   g_h2);
    cudaGetSymbolAddress((void**)&p_mid,  g_mid);
    cudaGetSymbolAddress((void**)&p_bcat, g_bcat);
    cudaGetSymbolAddress((void**)&p_wT,   g_wT);

    cudaFuncSetAttribute(tgemm_kernel,
                         cudaFuncAttributeMaxDynamicSharedMemorySize, SMEM_GEMM);

    // 0. weight transposes -> [N][K] K-major (qkvT = wqT|wkT|wvT stacked)
    transpose_kernel<<<dim3(16, 16), 256>>>(wq,    p_wT + WT_QKV,             C_,   C_);
    transpose_kernel<<<dim3(16, 16), 256>>>(wk,    p_wT + WT_QKV + C_*C_,     C_,   C_);
    transpose_kernel<<<dim3(16, 16), 256>>>(wv,    p_wT + WT_QKV + 2*C_*C_,   C_,   C_);
    transpose_kernel<<<dim3(16, 16), 256>>>(wo,    p_wT + WT_O,               C_,   C_);
    transpose_kernel<<<dim3(64, 16), 256>>>(wi,    p_wT + WT_I,               C_,   MLPD);
    transpose_kernel<<<dim3(16, 64), 256>>>(w_out, p_wT + WT_OUT,             MLPD, C_);
    bcat_kernel<<<(C_ + 255) / 256, 256>>>(bq, bk, bv, p_bcat);

    // 1. LN1 + cyclic shift + window partition (gather)
    ln_kernel<<<MTOK, 128>>>(x, g1, b1, p_win, 1);

    // 2. fused QKV projection -> g_mid as [MTOK][1536]
    dim3 gQKV(C3 / BN, MTOK / BM);
    tgemm_kernel<<<gQKV, 256, SMEM_GEMM>>>(p_win, p_wT + WT_QKV, p_bcat, p_mid,
                                           MTOK, C3, C_, 0, nullptr);

    // 3. windowed attention (scores + bias + mask + softmax + PV)
    attn_kernel<<<NWIN * HEADS_, 128>>>(p_mid, rel_table, rel_index, p_ctx);

    // 4. output projection + window reverse + un-shift scatter + residual(x)
    dim3 gC(C_ / BN, MTOK / BM);
    tgemm_kernel<<<gC, 256, SMEM_GEMM>>>(p_ctx, p_wT + WT_O, bo, p_x1,
                                         MTOK, C_, C_, 3, x);

    // 5. LN2
    ln_kernel<<<MTOK, 128>>>(p_x1, g2, b2, p_h2, 0);

    // 6. MLP up-projection + exact GELU
    dim3 gM(MLPD / BN, MTOK / BM);
    tgemm_kernel<<<gM, 256, SMEM_GEMM>>>(p_h2, p_wT + WT_I, bi, p_mid,
                                         MTOK, MLPD, C_, 1, nullptr);

    // 7. MLP down-projection + residual(x1) -> final output
    tgemm_kernel<<<gC, 256, SMEM_GEMM>>>(p_mid, p_wT + WT_OUT, b_out, out,
                                         MTOK, C_, MLPD, 2, p_x1);
}

// round 12
// speedup vs baseline: 1.2835x; 1.0330x over previous
#include <cuda_runtime.h>
#include <math.h>
#include <stdint.h>

// Problem constants
#define BATCH   64
#define HDIM    28
#define WDIM    28
#define C_      512
#define HEADS_  16
#define WS_     7
#define SHIFT_  3
#define MLPD    2048
#define HD_     32
#define W2_     49
#define NW_     16
#define HW_     784
#define MTOK    50176   // BATCH*HW
#define NWIN    1024    // BATCH*NW
#define C3      1536    // 3*C_ fused qkv width

// Scratch (device globals: no allocation allowed in kernel_launch)
__device__ float g_win[MTOK * C_];
__device__ float g_ctx[MTOK * C_];
__device__ float g_x1[MTOK * C_];
__device__ float g_h2[MTOK * C_];
__device__ float g_mid[(size_t)MTOK * MLPD];   // also holds fused qkv [MTOK][1536]
__device__ float g_bcat[C3];
// Transposed (K-major, [N][K]) weights: qkvT | woT | wiT | woutT
#define WT_QKV 0
#define WT_O   (C3 * C_)
#define WT_I   (WT_O + C_ * C_)
#define WT_OUT (WT_I + MLPD * C_)
__device__ float g_wT[WT_OUT + C_ * MLPD];

// Map window-partition row m -> token row in the unshifted [B,H*W] layout.
__device__ __forceinline__ int map_row(int m) {
    int bb  = m / HW_;
    int rem = m - bb * HW_;
    int w   = rem / W2_;
    int t   = rem - w * W2_;
    int wh = w >> 2, ww = w & 3;
    int th = t / WS_, tw = t - th * WS_;
    int r = wh * WS_ + th + SHIFT_; if (r >= HDIM) r -= HDIM;
    int c = ww * WS_ + tw + SHIFT_; if (c >= WDIM) c -= WDIM;
    return bb * HW_ + r * WDIM + c;
}

// Tiled transpose: out[Cc][R] = in[R][Cc]^T. Dims multiples of 32.
__global__ __launch_bounds__(256) void transpose_kernel(
    const float* __restrict__ in, float* __restrict__ out, int R, int Cc)
{
    __shared__ float t[32][33];
    int bx = blockIdx.x * 32, by = blockIdx.y * 32;
    int tx = threadIdx.x & 31, ty = threadIdx.x >> 5;
    #pragma unroll
    for (int j = 0; j < 32; j += 8)
        t[ty + j][tx] = in[(size_t)(by + ty + j) * Cc + bx + tx];
    __syncthreads();
    #pragma unroll
    for (int j = 0; j < 32; j += 8)
        out[(size_t)(bx + ty + j) * R + by + tx] = t[tx][ty + j];
}

// Concat qkv biases
__global__ __launch_bounds__(256) void bcat_kernel(
    const float* __restrict__ bq, const float* __restrict__ bk,
    const float* __restrict__ bv, float* __restrict__ bcat)
{
    int idx = blockIdx.x * 256 + threadIdx.x;
    if (idx < C_) {
        bcat[idx        ] = bq[idx];
        bcat[idx + C_   ] = bk[idx];
        bcat[idx + 2*C_ ] = bv[idx];
    }
}

// LayerNorm over C=512, one block per token row.
__global__ __launch_bounds__(128) void ln_kernel(
    const float* __restrict__ in, const float* __restrict__ g,
    const float* __restrict__ b, float* __restrict__ out, int gather)
{
    int m = blockIdx.x;
    int src = gather ? map_row(m) : m;
    int tid = threadIdx.x;

    float4 xv = ((const float4*)(in + (size_t)src * C_))[tid];
    float s  = xv.x + xv.y + xv.z + xv.w;
    float s2 = xv.x*xv.x + xv.y*xv.y + xv.z*xv.z + xv.w*xv.w;
    #pragma unroll
    for (int off = 16; off; off >>= 1) {
        s  += __shfl_xor_sync(0xffffffffu, s,  off);
        s2 += __shfl_xor_sync(0xffffffffu, s2, off);
    }
    __shared__ float red[8];
    int wid = tid >> 5;
    if ((tid & 31) == 0) { red[wid] = s; red[4 + wid] = s2; }
    __syncthreads();
    s  = red[0] + red[1] + red[2] + red[3];
    s2 = red[4] + red[5] + red[6] + red[7];
    float mu   = s * (1.0f / C_);
    float var  = fmaf(-mu, mu, s2 * (1.0f / C_));
    float rstd = rsqrtf(var + 1e-5f);

    float4 gv = ((const float4*)g)[tid];
    float4 bv = ((const float4*)b)[tid];
    float4 o;
    o.x = (xv.x - mu) * rstd * gv.x + bv.x;
    o.y = (xv.y - mu) * rstd * gv.y + bv.y;
    o.z = (xv.z - mu) * rstd * gv.z + bv.z;
    o.w = (xv.w - mu) * rstd * gv.w + bv.w;
    ((float4*)(out + (size_t)m * C_))[tid] = o;
}

// ---------------------------------------------------------------------------
// TF32 tensor-core GEMM, 5-stage cp.async pipeline, ldmatrix A AND B frags.
// ---------------------------------------------------------------------------
#define BM 128
#define BN 128
#define BKT 16
#define ASTR 20    // row stride (floats): conflict-free for LDSM phases
#define NSTAGE 5
#define AFLOATS (BM * ASTR)            // 2560
#define STAGEF  (2 * AFLOATS)          // 5120 floats = 20480 B
#define SMEM_GEMM (NSTAGE * STAGEF * 4)  // 102400 B

__device__ __forceinline__ void cpa16(uint32_t smem_dst, const void* gsrc) {
    asm volatile("cp.async.cg.shared.global [%0], [%1], 16;\n"
                 :: "r"(smem_dst), "l"(gsrc));
}

__device__ __forceinline__ void mma_tf32(float c[4], uint32_t a0, uint32_t a1,
                                         uint32_t a2, uint32_t a3,
                                         uint32_t b0, uint32_t b1) {
    asm volatile(
        "mma.sync.aligned.m16n8k8.row.col.f32.tf32.tf32.f32 "
        "{%0,%1,%2,%3}, {%4,%5,%6,%7}, {%8,%9}, {%0,%1,%2,%3};"
        : "+f"(c[0]), "+f"(c[1]), "+f"(c[2]), "+f"(c[3])
        : "r"(a0), "r"(a1), "r"(a2), "r"(a3), "r"(b0), "r"(b1));
}

__device__ __forceinline__ void ldsm4(uint32_t* a, uint32_t addr) {
    asm volatile("ldmatrix.sync.aligned.m8n8.x4.shared.b16 {%0,%1,%2,%3}, [%4];"
                 : "=r"(a[0]), "=r"(a[1]), "=r"(a[2]), "=r"(a[3]) : "r"(addr));
}

__global__ __launch_bounds__(256) void tgemm_kernel(
    const float* __restrict__ A, const float* __restrict__ Bt,
    const float* __restrict__ bias, float* __restrict__ C,
    int M, int N, int K, int mode, const float* __restrict__ res)
{
    extern __shared__ float sm[];

    const int cRow = blockIdx.y, cCol = blockIdx.x;
    const int tid  = threadIdx.x;
    const int wid  = tid >> 5;
    const int lane = tid & 31;
    const int wm   = wid >> 2;       // 0..1
    const int wn   = wid & 3;        // 0..3
    const int grp  = lane >> 2;      // 0..7
    const int tig  = lane & 3;       // 0..3

    const int lrowA = (lane & 7) + ((lane >> 3) & 1) * 8;
    const int lcolA = (lane >> 4) * 4;
    const int lrowB = (lane & 7) + (lane >> 4) * 8;
    const int lcolB = ((lane >> 3) & 1) * 4;

    const float* Ab = A  + (size_t)cRow * BM * K;
    const float* Bb = Bt + (size_t)cCol * BN * K;

    uint32_t smem_base = (uint32_t)__cvta_generic_to_shared(sm);
    const uint32_t aofs = (uint32_t)(((wm * 64 + lrowA) * ASTR + lcolA) * 4);
    const uint32_t bofs = (uint32_t)(AFLOATS * 4) +
                          (uint32_t)(((wn * 32 + lrowB) * ASTR + lcolB) * 4);

    float c[4][4][4] = {};

    auto load_tile = [&](int t, int s) {
        const int k0 = t * BKT;
        uint32_t abase = smem_base + (uint32_t)(s * STAGEF * 4);
        uint32_t bbase = abase + AFLOATS * 4;
        #pragma unroll
        for (int cc = 0; cc < 2; cc++) {
            int id = tid * 2 + cc;
            int r = id >> 2, kk = (id & 3) * 4;
            cpa16(abase + (uint32_t)((r * ASTR + kk) * 4),
                  Ab + (size_t)r * K + k0 + kk);
            cpa16(bbase + (uint32_t)((r * ASTR + kk) * 4),
                  Bb + (size_t)r * K + k0 + kk);
        }
    };

    const int T = K / BKT;
    #pragma unroll
    for (int s = 0; s < NSTAGE - 1; s++) {
        load_tile(s, s);
        asm volatile("cp.async.commit_group;");
    }

    int ci = 0;
    int pi = NSTAGE - 1;
    for (int i = 0; i < T; i++) {
        asm volatile("cp.async.wait_group %0;" :: "n"(NSTAGE - 2));
        __syncthreads();

        if (i + NSTAGE - 1 < T) load_tile(i + NSTAGE - 1, pi);
        asm volatile("cp.async.commit_group;");

        const uint32_t stage = smem_base + (uint32_t)(ci * STAGEF * 4);
        const uint32_t aStage = stage + aofs;
        const uint32_t bStage = stage + bofs;

        #pragma unroll
        for (int ks = 0; ks < 2; ks++) {
            uint32_t a[4][4], b[4][2];
            #pragma unroll
            for (int mi = 0; mi < 4; mi++)
                ldsm4(a[mi], aStage + (uint32_t)(mi * 16 * ASTR * 4 + ks * 32));
            #pragma unroll
            for (int p = 0; p < 2; p++) {
                uint32_t t4[4];
                ldsm4(t4, bStage + (uint32_t)(p * 16 * ASTR * 4 + ks * 32));
                b[p*2    ][0] = t4[0];
                b[p*2    ][1] = t4[1];
                b[p*2 + 1][0] = t4[2];
                b[p*2 + 1][1] = t4[3];
            }
            #pragma unroll
            for (int mi = 0; mi < 4; mi++)
                #pragma unroll
                for (int ni = 0; ni < 4; ni++)
                    mma_tf32(c[mi][ni], a[mi][0], a[mi][1], a[mi][2], a[mi][3],
                             b[ni][0], b[ni][1]);
        }
        ci = (ci + 1 == NSTAGE) ? 0 : ci + 1;
        pi = (pi + 1 == NSTAGE) ? 0 : pi + 1;
    }

    // epilogue
    #pragma unroll
    for (int mi = 0; mi < 4; mi++) {
        #pragma unroll
        for (int rr = 0; rr < 2; rr++) {
            int m = cRow * BM + wm * 64 + mi * 16 + grp + rr * 8;
            int outm = (mode == 3) ? map_row(m) : m;
            #pragma unroll
            for (int ni = 0; ni < 4; ni++) {
                int n = cCol * BN + wn * 32 + ni * 8 + tig * 2;
                float v0 = c[mi][ni][rr * 2 + 0] + bias[n];
                float v1 = c[mi][ni][rr * 2 + 1] + bias[n + 1];
                if (mode == 1) {
                    v0 = 0.5f * v0 * (1.0f + erff(v0 * 0.70710678118654752f));
                    v1 = 0.5f * v1 * (1.0f + erff(v1 * 0.70710678118654752f));
                } else if (mode == 2) {
                    v0 += res[(size_t)m * N + n];
                    v1 += res[(size_t)m * N + n + 1];
                } else if (mode == 3) {
                    v0 += res[(size_t)outm * N + n];
                    v1 += res[(size_t)outm * N + n + 1];
                }
                C[(size_t)outm * N + n]     = v0;
                C[(size_t)outm * N + n + 1] = v1;
            }
        }
    }
}

// ---------------------------------------------------------------------------
// Windowed attention on tensor cores (mma.m16n8k8.tf32).
// One block (128 thr = 4 warps) per (window, head). Warp w owns S rows
// [16w, 16w+16). QK^T and PV both run on HMMA; softmax stays fp32.
// q/k staged at row stride 36 (conflict-free ldsm); probs (64x60) and V^T
// (32x60) at stride 60. Pad regions zeroed so k-padding contributes 0.
// ---------------------------------------------------------------------------
#define QK_STR 36
#define SC_STR 60
__global__ __launch_bounds__(128) void attn_kernel(
    const float* __restrict__ qkv, const float* __restrict__ rel_table,
    const int* __restrict__ rel_index, float* __restrict__ ctx)
{
    __shared__ float qs[64 * QK_STR];
    __shared__ float karr[64 * QK_STR];
    __shared__ float vsT[32 * SC_STR];
    __shared__ float sc[64 * SC_STR];
    __shared__ int   grp[W2_];

    int blk  = blockIdx.x;
    int head = blk & (HEADS_ - 1);
    int win  = blk >> 4;
    int w    = win & (NW_ - 1);
    int tid  = threadIdx.x;
    int wid  = tid >> 5;
    int lane = tid & 31;

    // Zero all tiles (pad rows/cols must be 0 or benign).
    {
        float4 z = make_float4(0.f, 0.f, 0.f, 0.f);
        for (int i = tid; i < (64 * QK_STR) / 4; i += 128) {
            ((float4*)qs)[i] = z;
            ((float4*)karr)[i] = z;
        }
        for (int i = tid; i < (32 * SC_STR) / 4; i += 128) ((float4*)vsT)[i] = z;
        for (int i = tid; i < (64 * SC_STR) / 4; i += 128) ((float4*)sc)[i] = z;
    }
    __syncthreads();

    const size_t qbase = (size_t)win * W2_ * C3 + head * HD_;
    for (int idx = tid; idx < W2_ * 8; idx += 128) {
        int t = idx >> 3, dc = idx & 7;
        const float* p = qkv + qbase + (size_t)t * C3 + dc * 4;
        float4 qv = *(const float4*)(p);
        float4 kv = *(const float4*)(p + C_);
        float4 vv = *(const float4*)(p + 2 * C_);
        *(float4*)&qs[t * QK_STR + dc * 4] = qv;
        *(float4*)&karr[t * QK_STR + dc * 4] = kv;
        int d0 = dc * 4;
        vsT[(d0    ) * SC_STR + t] = vv.x;
        vsT[(d0 + 1) * SC_STR + t] = vv.y;
        vsT[(d0 + 2) * SC_STR + t] = vv.z;
        vsT[(d0 + 3) * SC_STR + t] = vv.w;
    }
    if (tid < W2_) {
        int wh = w >> 2, ww = w & 3;
        int r = wh * WS_ + tid / WS_;
        int c = ww * WS_ + tid % WS_;
        int br = (r < HDIM - WS_) ? 0 : ((r < HDIM - SHIFT_) ? 1 : 2);
        int bc = (c < WDIM - WS_) ? 0 : ((c < WDIM - SHIFT_) ? 1 : 2);
        grp[tid] = br * 3 + bc;
    }
    __syncthreads();

    const float scale = 0.17677669529663687f; // 1/sqrt(32)
    const int m0 = wid * 16;
    const int lrowA = (lane & 7) + ((lane >> 3) & 1) * 8;
    const int lcolA = (lane >> 4) * 4;
    const int lrowB = (lane & 7) + (lane >> 4) * 8;
    const int lcolB = ((lane >> 3) & 1) * 4;
    const int rgrp  = lane >> 2;   // fragment row within 8
    const int tig   = lane & 3;

    // ---- Scores: S[16 x 56] per warp = Q[16 x 32] @ K^T ----
    {
        uint32_t qb = (uint32_t)__cvta_generic_to_shared(qs) +
                      (uint32_t)(((m0 + lrowA) * QK_STR + lcolA) * 4);
        uint32_t kb = (uint32_t)__cvta_generic_to_shared(karr) +
                      (uint32_t)((lrowB * QK_STR + lcolB) * 4);

        float c[7][4] = {};
        #pragma unroll
        for (int ksp = 0; ksp < 4; ksp++) {
            uint32_t a[4];
            ldsm4(a, qb + ksp * 32);
            uint32_t b[8][2];
            #pragma unroll
            for (int p = 0; p < 4; p++) {
                uint32_t t4[4];
                ldsm4(t4, kb + (uint32_t)(p * 16 * QK_STR * 4) + ksp * 32);
                b[p*2    ][0] = t4[0]; b[p*2    ][1] = t4[1];
                b[p*2 + 1][0] = t4[2]; b[p*2 + 1][1] = t4[3];
            }
            #pragma unroll
            for (int ni = 0; ni < 7; ni++)
                mma_tf32(c[ni], a[0], a[1], a[2], a[3], b[ni][0], b[ni][1]);
        }

        // epilogue: scale + rel-pos bias + shift mask -> sc
        #pragma unroll
        for (int ni = 0; ni < 7; ni++) {
            #pragma unroll
            for (int h = 0; h < 2; h++) {
                int i = m0 + rgrp + h * 8;
                if (i < W2_) {
                    #pragma unroll
                    for (int e = 0; e < 2; e++) {
                        int j = ni * 8 + tig * 2 + e;
                        if (j < W2_) {
                            float bias = rel_table[rel_index[i * W2_ + j] * HEADS_ + head];
                            float mask = (grp[i] != grp[j]) ? -100.0f : 0.0f;
                            sc[i * SC_STR + j] = c[ni][h * 2 + e] * scale + bias + mask;
                        }
                    }
                }
            }
        }
    }
    __syncthreads();

    // ---- Softmax per row (fp32, rows 0..48; pad cols stay 0) ----
    if (tid < W2_) {
        float mx = -1e30f;
        #pragma unroll 7
        for (int j = 0; j < W2_; j++) mx = fmaxf(mx, sc[tid * SC_STR + j]);
        float sum = 0.0f;
        #pragma unroll 7
        for (int j = 0; j < W2_; j++) {
            float e = __expf(sc[tid * SC_STR + j] - mx);
            sc[tid * SC_STR + j] = e;
            sum += e;
        }
        float inv = 1.0f / sum;
        #pragma unroll 7
        for (int j = 0; j < W2_; j++) sc[tid * SC_STR + j] *= inv;
    }
    __syncthreads();

    // ---- PV: O[16 x 32] per warp = P[16 x 56] @ V[56 x 32] ----
    {
        uint32_t pb = (uint32_t)__cvta_generic_to_shared(sc) +
                      (uint32_t)(((m0 + lrowA) * SC_STR + lcolA) * 4);
        uint32_t vb = (uint32_t)__cvta_generic_to_shared(vsT) +
                      (uint32_t)((lrowB * SC_STR + lcolB) * 4);

        float o[4][4] = {};
        #pragma unroll
        for (int kj = 0; kj < 7; kj++) {
            uint32_t a[4];
            ldsm4(a, pb + kj * 32);
            uint32_t b[4][2];
            #pragma unroll
            for (int p = 0; p < 2; p++) {
                uint32_t t4[4];
                ldsm4(t4, vb + (uint32_t)(p * 16 * SC_STR * 4) + kj * 32);
                b[p*2    ][0] = t4[0]; b[p*2    ][1] = t4[1];
                b[p*2 + 1][0] = t4[2]; b[p*2 + 1][1] = t4[3];
            }
            #pragma unroll
            for (int ni = 0; ni < 4; ni++)
                mma_tf32(o[ni], a[0], a[1], a[2], a[3], b[ni][0], b[ni][1]);
        }

        const size_t obase = (size_t)win * W2_ * C_ + head * HD_;
        #pragma unroll
        for (int ni = 0; ni < 4; ni++) {
            #pragma unroll
            for (int h = 0; h < 2; h++) {
                int i = m0 + rgrp + h * 8;
                if (i < W2_) {
                    int d = ni * 8 + tig * 2;
                    float2 val = make_float2(o[ni][h * 2], o[ni][h * 2 + 1]);
                    *(float2*)&ctx[obase + (size_t)i * C_ + d] = val;
                }
            }
        }
    }
}

extern "C" void kernel_launch(void* const* d_in, const int* in_sizes, int n_in,
                              void* d_out, int out_size)
{
    const float* x         = (const float*)d_in[0];
    const float* g1        = (const float*)d_in[1];
    const float* b1        = (const float*)d_in[2];
    const float* wq        = (const float*)d_in[3];
    const float* bq        = (const float*)d_in[4];
    const float* wk        = (const float*)d_in[5];
    const float* bk        = (const float*)d_in[6];
    const float* wv        = (const float*)d_in[7];
    const float* bv        = (const float*)d_in[8];
    const float* rel_table = (const float*)d_in[9];
    const float* wo        = (const float*)d_in[10];
    const float* bo        = (const float*)d_in[11];
    const float* g2        = (const float*)d_in[12];
    const float* b2        = (const float*)d_in[13];
    const float* wi        = (const float*)d_in[14];
    const float* bi        = (const float*)d_in[15];
    const float* w_out     = (const float*)d_in[16];
    const float* b_out     = (const float*)d_in[17];
    const int*   rel_index = (const int*)d_in[18];
    float* out = (float*)d_out;

    float *p_win, *p_ctx, *p_x1, *p_h2, *p_mid, *p_bcat, *p_wT;
    cudaGetSymbolAddress((void**)&p_win,  g_win);
    cudaGetSymbolAddress((void**)&p_ctx,  g_ctx);
    cudaGetSymbolAddress((void**)&p_x1,   g_x1);
    cudaGetSymbolAddress((void**)&p_h2,   g_h2);
    cudaGetSymbolAddress((void**)&p_mid,  g_mid);
    cudaGetSymbolAddress((void**)&p_bcat, g_bcat);
    cudaGetSymbolAddress((void**)&p_wT,   g_wT);

    cudaFuncSetAttribute(tgemm_kernel,
                         cudaFuncAttributeMaxDynamicSharedMemorySize, SMEM_GEMM);

    // 0. weight transposes -> [N][K] K-major (qkvT = wqT|wkT|wvT stacked)
    transpose_kernel<<<dim3(16, 16), 256>>>(wq,    p_wT + WT_QKV,             C_,   C_);
    transpose_kernel<<<dim3(16, 16), 256>>>(wk,    p_wT + WT_QKV + C_*C_,     C_,   C_);
    transpose_kernel<<<dim3(16, 16), 256>>>(wv,    p_wT + WT_QKV + 2*C_*C_,   C_,   C_);
    transpose_kernel<<<dim3(16, 16), 256>>>(wo,    p_wT + WT_O,               C_,   C_);
    transpose_kernel<<<dim3(64, 16), 256>>>(wi,    p_wT + WT_I,               C_,   MLPD);
    transpose_kernel<<<dim3(16, 64), 256>>>(w_out, p_wT + WT_OUT,             MLPD, C_);
    bcat_kernel<<<(C_ + 255) / 256, 256>>>(bq, bk, bv, p_bcat);

    // 1. LN1 + cyclic shift + window partition (gather)
    ln_kernel<<<MTOK, 128>>>(x, g1, b1, p_win, 1);

    // 2. fused QKV projection -> g_mid as [MTOK][1536]
    dim3 gQKV(C3 / BN, MTOK / BM);
    tgemm_kernel<<<gQKV, 256, SMEM_GEMM>>>(p_win, p_wT + WT_QKV, p_bcat, p_mid,
                                           MTOK, C3, C_, 0, nullptr);

    // 3. windowed attention (tensor-core scores + softmax + tensor-core PV)
    attn_kernel<<<NWIN * HEADS_, 128>>>(p_mid, rel_table, rel_index, p_ctx);

    // 4. output projection + window reverse + un-shift scatter + residual(x)
    dim3 gC(C_ / BN, MTOK / BM);
    tgemm_kernel<<<gC, 256, SMEM_GEMM>>>(p_ctx, p_wT + WT_O, bo, p_x1,
                                         MTOK, C_, C_, 3, x);

    // 5. LN2
    ln_kernel<<<MTOK, 128>>>(p_x1, g2, b2, p_h2, 0);

    // 6. MLP up-projection + exact GELU
    dim3 gM(MLPD / BN, MTOK / BM);
    tgemm_kernel<<<gM, 256, SMEM_GEMM>>>(p_h2, p_wT + WT_I, bi, p_mid,
                                         MTOK, MLPD, C_, 1, nullptr);

    // 7. MLP down-projection + residual(x1) -> final output
    tgemm_kernel<<<gC, 256, SMEM_GEMM>>>(p_mid, p_wT + WT_OUT, b_out, out,
                                         MTOK, C_, MLPD, 2, p_x1);
}

// round 13
// speedup vs baseline: 1.8296x; 1.4255x over previous
#include <cuda_runtime.h>
#include <cuda_fp16.h>
#include <math.h>
#include <stdint.h>

// Problem constants
#define BATCH   64
#define HDIM    28
#define WDIM    28
#define C_      512
#define HEADS_  16
#define WS_     7
#define SHIFT_  3
#define MLPD    2048
#define HD_     32
#define W2_     49
#define NW_     16
#define HW_     784
#define MTOK    50176   // BATCH*HW
#define NWIN    1024    // BATCH*NW
#define C3      1536    // 3*C_ fused qkv width

// Scratch (device globals: no allocation allowed in kernel_launch)
__device__ __half g_win[MTOK * C_];
__device__ __half g_qkv[(size_t)MTOK * MLPD];  // fused qkv [MTOK][1536]; also mid
__device__ __half g_ctx[MTOK * C_];
__device__ __half g_h2[MTOK * C_];
__device__ float  g_x1[MTOK * C_];
__device__ float  g_bcat[C3];
// Transposed (K-major, [N][K]) fp16 weights: qkvT | woT | wiT | woutT
#define WT_QKV 0
#define WT_O   (C3 * C_)
#define WT_I   (WT_O + C_ * C_)
#define WT_OUT (WT_I + MLPD * C_)
__device__ __half g_wT[WT_OUT + C_ * MLPD];

// Map window-partition row m -> token row in the unshifted [B,H*W] layout.
__device__ __forceinline__ int map_row(int m) {
    int bb  = m / HW_;
    int rem = m - bb * HW_;
    int w   = rem / W2_;
    int t   = rem - w * W2_;
    int wh = w >> 2, ww = w & 3;
    int th = t / WS_, tw = t - th * WS_;
    int r = wh * WS_ + th + SHIFT_; if (r >= HDIM) r -= HDIM;
    int c = ww * WS_ + tw + SHIFT_; if (c >= WDIM) c -= WDIM;
    return bb * HW_ + r * WDIM + c;
}

// Tiled transpose + fp32->fp16: out[Cc][R] = half(in[R][Cc]^T).
__global__ __launch_bounds__(256) void transpose_kernel(
    const float* __restrict__ in, __half* __restrict__ out, int R, int Cc)
{
    __shared__ float t[32][33];
    int bx = blockIdx.x * 32, by = blockIdx.y * 32;
    int tx = threadIdx.x & 31, ty = threadIdx.x >> 5;
    #pragma unroll
    for (int j = 0; j < 32; j += 8)
        t[ty + j][tx] = in[(size_t)(by + ty + j) * Cc + bx + tx];
    __syncthreads();
    #pragma unroll
    for (int j = 0; j < 32; j += 8)
        out[(size_t)(bx + ty + j) * R + by + tx] = __float2half(t[tx][ty + j]);
}

// Concat qkv biases (fp32)
__global__ __launch_bounds__(256) void bcat_kernel(
    const float* __restrict__ bq, const float* __restrict__ bk,
    const float* __restrict__ bv, float* __restrict__ bcat)
{
    int idx = blockIdx.x * 256 + threadIdx.x;
    if (idx < C_) {
        bcat[idx        ] = bq[idx];
        bcat[idx + C_   ] = bk[idx];
        bcat[idx + 2*C_ ] = bv[idx];
    }
}

// LayerNorm over C=512, one block per token row; fp32 in, fp16 out.
__global__ __launch_bounds__(128) void ln_kernel(
    const float* __restrict__ in, const float* __restrict__ g,
    const float* __restrict__ b, __half* __restrict__ out, int gather)
{
    int m = blockIdx.x;
    int src = gather ? map_row(m) : m;
    int tid = threadIdx.x;

    float4 xv = ((const float4*)(in + (size_t)src * C_))[tid];
    float s  = xv.x + xv.y + xv.z + xv.w;
    float s2 = xv.x*xv.x + xv.y*xv.y + xv.z*xv.z + xv.w*xv.w;
    #pragma unroll
    for (int off = 16; off; off >>= 1) {
        s  += __shfl_xor_sync(0xffffffffu, s,  off);
        s2 += __shfl_xor_sync(0xffffffffu, s2, off);
    }
    __shared__ float red[8];
    int wid = tid >> 5;
    if ((tid & 31) == 0) { red[wid] = s; red[4 + wid] = s2; }
    __syncthreads();
    s  = red[0] + red[1] + red[2] + red[3];
    s2 = red[4] + red[5] + red[6] + red[7];
    float mu   = s * (1.0f / C_);
    float var  = fmaf(-mu, mu, s2 * (1.0f / C_));
    float rstd = rsqrtf(var + 1e-5f);

    float4 gv = ((const float4*)g)[tid];
    float4 bv = ((const float4*)b)[tid];
    __half2 o01 = __floats2half2_rn((xv.x - mu) * rstd * gv.x + bv.x,
                                    (xv.y - mu) * rstd * gv.y + bv.y);
    __half2 o23 = __floats2half2_rn((xv.z - mu) * rstd * gv.z + bv.z,
                                    (xv.w - mu) * rstd * gv.w + bv.w);
    __half2* op = (__half2*)(out + (size_t)m * C_ + tid * 4);
    op[0] = o01;
    op[1] = o23;
}

// ---------------------------------------------------------------------------
// FP16 tensor-core GEMM (mma.m16n8k16, fp32 accum), 5-stage cp.async ring,
// ldmatrix A and B fragments. C[M,N] = A[M,K] @ Bt[N,K]^T + bias (fp32 math).
// Row layout in smem: 80 bytes/row = 32 halves data + 8 pad (same bank
// pattern as the proven tf32 version). Each stage covers K=32.
// mode 0: plain  1: exact GELU  2: += res[m]  3: scatter map_row(m), += res
// half_out: 1 -> store __half, 0 -> store float.
// ---------------------------------------------------------------------------
#define BM 128
#define BN 128
#define BKH 32                   // K halves per stage
#define ROWB 80                  // bytes per smem row
#define A_BYTES (BM * ROWB)      // 10240
#define NSTAGE 5
#define STAGE_BYTES (2 * A_BYTES)           // 20480
#define SMEM_GEMM (NSTAGE * STAGE_BYTES)    // 102400

__device__ __forceinline__ void cpa16(uint32_t smem_dst, const void* gsrc) {
    asm volatile("cp.async.cg.shared.global [%0], [%1], 16;\n"
                 :: "r"(smem_dst), "l"(gsrc));
}

__device__ __forceinline__ void mma_f16(float c[4], uint32_t a0, uint32_t a1,
                                        uint32_t a2, uint32_t a3,
                                        uint32_t b0, uint32_t b1) {
    asm volatile(
        "mma.sync.aligned.m16n8k16.row.col.f32.f16.f16.f32 "
        "{%0,%1,%2,%3}, {%4,%5,%6,%7}, {%8,%9}, {%0,%1,%2,%3};"
        : "+f"(c[0]), "+f"(c[1]), "+f"(c[2]), "+f"(c[3])
        : "r"(a0), "r"(a1), "r"(a2), "r"(a3), "r"(b0), "r"(b1));
}

__device__ __forceinline__ void ldsm4(uint32_t* a, uint32_t addr) {
    asm volatile("ldmatrix.sync.aligned.m8n8.x4.shared.b16 {%0,%1,%2,%3}, [%4];"
                 : "=r"(a[0]), "=r"(a[1]), "=r"(a[2]), "=r"(a[3]) : "r"(addr));
}

__global__ __launch_bounds__(256) void tgemm_kernel(
    const __half* __restrict__ A, const __half* __restrict__ Bt,
    const float* __restrict__ bias, void* __restrict__ Cout,
    int M, int N, int K, int mode, const float* __restrict__ res, int half_out)
{
    extern __shared__ char sm[];

    const int cRow = blockIdx.y, cCol = blockIdx.x;
    const int tid  = threadIdx.x;
    const int wid  = tid >> 5;
    const int lane = tid & 31;
    const int wm   = wid >> 2;       // 0..1
    const int wn   = wid & 3;        // 0..3
    const int grp  = lane >> 2;      // 0..7
    const int tig  = lane & 3;       // 0..3

    // ldmatrix lane address components (A: m16xk16 x4; B: n16xk16 x4)
    const int lrowA = (lane & 7) + ((lane >> 3) & 1) * 8;
    const int lcbA  = (lane >> 4) * 16;           // k-half byte offset 0/16
    const int lrowB = (lane & 7) + (lane >> 4) * 8;
    const int lcbB  = ((lane >> 3) & 1) * 16;

    const __half* Ab = A  + (size_t)cRow * BM * K;
    const __half* Bb = Bt + (size_t)cCol * BN * K;

    uint32_t smem_base = (uint32_t)__cvta_generic_to_shared(sm);
    const uint32_t aofs = (uint32_t)((wm * 64 + lrowA) * ROWB + lcbA);
    const uint32_t bofs = (uint32_t)A_BYTES +
                          (uint32_t)((wn * 32 + lrowB) * ROWB + lcbB);

    float c[4][4][4] = {};

    // Per stage: 128 rows x 64B data per tile; 4 chunks/row; 512 chunks = 256thr x 2.
    auto load_tile = [&](int t, int s) {
        const int k0 = t * BKH;
        uint32_t abase = smem_base + (uint32_t)(s * STAGE_BYTES);
        uint32_t bbase = abase + A_BYTES;
        #pragma unroll
        for (int cc = 0; cc < 2; cc++) {
            int id = tid * 2 + cc;
            int r = id >> 2, kc = id & 3;   // kc: 16B chunk = 8 halves
            cpa16(abase + (uint32_t)(r * ROWB + kc * 16),
                  Ab + (size_t)r * K + k0 + kc * 8);
            cpa16(bbase + (uint32_t)(r * ROWB + kc * 16),
                  Bb + (size_t)r * K + k0 + kc * 8);
        }
    };

    const int T = K / BKH;
    #pragma unroll
    for (int s = 0; s < NSTAGE - 1; s++) {
        load_tile(s, s);
        asm volatile("cp.async.commit_group;");
    }

    int ci = 0;
    int pi = NSTAGE - 1;
    for (int i = 0; i < T; i++) {
        asm volatile("cp.async.wait_group %0;" :: "n"(NSTAGE - 2));
        __syncthreads();

        if (i + NSTAGE - 1 < T) load_tile(i + NSTAGE - 1, pi);
        asm volatile("cp.async.commit_group;");

        const uint32_t stage = smem_base + (uint32_t)(ci * STAGE_BYTES);
        const uint32_t aStage = stage + aofs;
        const uint32_t bStage = stage + bofs;

        #pragma unroll
        for (int ks = 0; ks < 2; ks++) {          // two k16 steps per stage
            uint32_t a[4][4], b[4][2];
            #pragma unroll
            for (int mi = 0; mi < 4; mi++)
                ldsm4(a[mi], aStage + (uint32_t)(mi * 16 * ROWB + ks * 32));
            #pragma unroll
            for (int p = 0; p < 2; p++) {
                uint32_t t4[4];
                ldsm4(t4, bStage + (uint32_t)(p * 16 * ROWB + ks * 32));
                b[p*2    ][0] = t4[0];
                b[p*2    ][1] = t4[1];
                b[p*2 + 1][0] = t4[2];
                b[p*2 + 1][1] = t4[3];
            }
            #pragma unroll
            for (int mi = 0; mi < 4; mi++)
                #pragma unroll
                for (int ni = 0; ni < 4; ni++)
                    mma_f16(c[mi][ni], a[mi][0], a[mi][1], a[mi][2], a[mi][3],
                            b[ni][0], b[ni][1]);
        }
        ci = (ci + 1 == NSTAGE) ? 0 : ci + 1;
        pi = (pi + 1 == NSTAGE) ? 0 : pi + 1;
    }

    // epilogue (fp32 math)
    #pragma unroll
    for (int mi = 0; mi < 4; mi++) {
        #pragma unroll
        for (int rr = 0; rr < 2; rr++) {
            int m = cRow * BM + wm * 64 + mi * 16 + grp + rr * 8;
            int outm = (mode == 3) ? map_row(m) : m;
            #pragma unroll
            for (int ni = 0; ni < 4; ni++) {
                int n = cCol * BN + wn * 32 + ni * 8 + tig * 2;
                float v0 = c[mi][ni][rr * 2 + 0] + bias[n];
                float v1 = c[mi][ni][rr * 2 + 1] + bias[n + 1];
                if (mode == 1) {
                    v0 = 0.5f * v0 * (1.0f + erff(v0 * 0.70710678118654752f));
                    v1 = 0.5f * v1 * (1.0f + erff(v1 * 0.70710678118654752f));
                } else if (mode == 2) {
                    v0 += res[(size_t)m * N + n];
                    v1 += res[(size_t)m * N + n + 1];
                } else if (mode == 3) {
                    v0 += res[(size_t)outm * N + n];
                    v1 += res[(size_t)outm * N + n + 1];
                }
                if (half_out) {
                    *(__half2*)((__half*)Cout + (size_t)outm * N + n) =
                        __floats2half2_rn(v0, v1);
                } else {
                    float* Cp = (float*)Cout + (size_t)outm * N + n;
                    Cp[0] = v0;
                    Cp[1] = v1;
                }
            }
        }
    }
}

// ---------------------------------------------------------------------------
// Windowed attention on tensor cores (mma.m16n8k8.tf32), fp16 I/O.
// One block (128 thr = 4 warps) per (window, head).
// ---------------------------------------------------------------------------
#define QK_STR 36
#define SC_STR 60

__device__ __forceinline__ void mma_tf32(float c[4], uint32_t a0, uint32_t a1,
                                         uint32_t a2, uint32_t a3,
                                         uint32_t b0, uint32_t b1) {
    asm volatile(
        "mma.sync.aligned.m16n8k8.row.col.f32.tf32.tf32.f32 "
        "{%0,%1,%2,%3}, {%4,%5,%6,%7}, {%8,%9}, {%0,%1,%2,%3};"
        : "+f"(c[0]), "+f"(c[1]), "+f"(c[2]), "+f"(c[3])
        : "r"(a0), "r"(a1), "r"(a2), "r"(a3), "r"(b0), "r"(b1));
}

__global__ __launch_bounds__(128) void attn_kernel(
    const __half* __restrict__ qkv, const float* __restrict__ rel_table,
    const int* __restrict__ rel_index, __half* __restrict__ ctx)
{
    __shared__ float qs[64 * QK_STR];
    __shared__ float karr[64 * QK_STR];
    __shared__ float vsT[32 * SC_STR];
    __shared__ float sc[64 * SC_STR];
    __shared__ int   grp[W2_];

    int blk  = blockIdx.x;
    int head = blk & (HEADS_ - 1);
    int win  = blk >> 4;
    int w    = win & (NW_ - 1);
    int tid  = threadIdx.x;
    int wid  = tid >> 5;
    int lane = tid & 31;

    {
        float4 z = make_float4(0.f, 0.f, 0.f, 0.f);
        for (int i = tid; i < (64 * QK_STR) / 4; i += 128) {
            ((float4*)qs)[i] = z;
            ((float4*)karr)[i] = z;
        }
        for (int i = tid; i < (32 * SC_STR) / 4; i += 128) ((float4*)vsT)[i] = z;
        for (int i = tid; i < (64 * SC_STR) / 4; i += 128) ((float4*)sc)[i] = z;
    }
    __syncthreads();

    const size_t qbase = (size_t)win * W2_ * C3 + head * HD_;
    for (int idx = tid; idx < W2_ * 4; idx += 128) {
        int t = idx >> 2, dc = idx & 3;          // dc: 8-half chunk
        const __half2* p = (const __half2*)(qkv + qbase + (size_t)t * C3 + dc * 8);
        #pragma unroll
        for (int u = 0; u < 4; u++) {
            float2 qv = __half22float2(p[u]);
            float2 kv = __half22float2(p[u + C_ / 2]);
            float2 vv = __half22float2(p[u + C_]);
            int d0 = dc * 8 + u * 2;
            qs[t * QK_STR + d0]       = qv.x;
            qs[t * QK_STR + d0 + 1]   = qv.y;
            karr[t * QK_STR + d0]     = kv.x;
            karr[t * QK_STR + d0 + 1] = kv.y;
            vsT[(d0    ) * SC_STR + t] = vv.x;
            vsT[(d0 + 1) * SC_STR + t] = vv.y;
        }
    }
    if (tid < W2_) {
        int wh = w >> 2, ww = w & 3;
        int r = wh * WS_ + tid / WS_;
        int c = ww * WS_ + tid % WS_;
        int br = (r < HDIM - WS_) ? 0 : ((r < HDIM - SHIFT_) ? 1 : 2);
        int bc = (c < WDIM - WS_) ? 0 : ((c < WDIM - SHIFT_) ? 1 : 2);
        grp[tid] = br * 3 + bc;
    }
    __syncthreads();

    const float scale = 0.17677669529663687f; // 1/sqrt(32)
    const int m0 = wid * 16;
    const int lrowA = (lane & 7) + ((lane >> 3) & 1) * 8;
    const int lcolA = (lane >> 4) * 4;
    const int lrowB = (lane & 7) + (lane >> 4) * 8;
    const int lcolB = ((lane >> 3) & 1) * 4;
    const int rgrp  = lane >> 2;
    const int tig   = lane & 3;

    // ---- Scores ----
    {
        uint32_t qb = (uint32_t)__cvta_generic_to_shared(qs) +
                      (uint32_t)(((m0 + lrowA) * QK_STR + lcolA) * 4);
        uint32_t kb = (uint32_t)__cvta_generic_to_shared(karr) +
                      (uint32_t)((lrowB * QK_STR + lcolB) * 4);

        float c[7][4] = {};
        #pragma unroll
        for (int ksp = 0; ksp < 4; ksp++) {
            uint32_t a[4];
            ldsm4(a, qb + ksp * 32);
            uint32_t b[8][2];
            #pragma unroll
            for (int p = 0; p < 4; p++) {
                uint32_t t4[4];
                ldsm4(t4, kb + (uint32_t)(p * 16 * QK_STR * 4) + ksp * 32);
                b[p*2    ][0] = t4[0]; b[p*2    ][1] = t4[1];
                b[p*2 + 1][0] = t4[2]; b[p*2 + 1][1] = t4[3];
            }
            #pragma unroll
            for (int ni = 0; ni < 7; ni++)
                mma_tf32(c[ni], a[0], a[1], a[2], a[3], b[ni][0], b[ni][1]);
        }

        #pragma unroll
        for (int ni = 0; ni < 7; ni++) {
            #pragma unroll
            for (int h = 0; h < 2; h++) {
                int i = m0 + rgrp + h * 8;
                if (i < W2_) {
                    #pragma unroll
                    for (int e = 0; e < 2; e++) {
                        int j = ni * 8 + tig * 2 + e;
                        if (j < W2_) {
                            float bias = rel_table[rel_index[i * W2_ + j] * HEADS_ + head];
                            float mask = (grp[i] != grp[j]) ? -100.0f : 0.0f;
                            sc[i * SC_STR + j] = c[ni][h * 2 + e] * scale + bias + mask;
                        }
                    }
                }
            }
        }
    }
    __syncthreads();

    // ---- Softmax ----
    if (tid < W2_) {
        float mx = -1e30f;
        #pragma unroll 7
        for (int j = 0; j < W2_; j++) mx = fmaxf(mx, sc[tid * SC_STR + j]);
        float sum = 0.0f;
        #pragma unroll 7
        for (int j = 0; j < W2_; j++) {
            float e = __expf(sc[tid * SC_STR + j] - mx);
            sc[tid * SC_STR + j] = e;
            sum += e;
        }
        float inv = 1.0f / sum;
        #pragma unroll 7
        for (int j = 0; j < W2_; j++) sc[tid * SC_STR + j] *= inv;
    }
    __syncthreads();

    // ---- PV ----
    {
        uint32_t pb = (uint32_t)__cvta_generic_to_shared(sc) +
                      (uint32_t)(((m0 + lrowA) * SC_STR + lcolA) * 4);
        uint32_t vb = (uint32_t)__cvta_generic_to_shared(vsT) +
                      (uint32_t)((lrowB * SC_STR + lcolB) * 4);

        float o[4][4] = {};
        #pragma unroll
        for (int kj = 0; kj < 7; kj++) {
            uint32_t a[4];
            ldsm4(a, pb + kj * 32);
            uint32_t b[4][2];
            #pragma unroll
            for (int p = 0; p < 2; p++) {
                uint32_t t4[4];
                ldsm4(t4, vb + (uint32_t)(p * 16 * SC_STR * 4) + kj * 32);
                b[p*2    ][0] = t4[0]; b[p*2    ][1] = t4[1];
                b[p*2 + 1][0] = t4[2]; b[p*2 + 1][1] = t4[3];
            }
            #pragma unroll
            for (int ni = 0; ni < 4; ni++)
                mma_tf32(o[ni], a[0], a[1], a[2], a[3], b[ni][0], b[ni][1]);
        }

        const size_t obase = (size_t)win * W2_ * C_ + head * HD_;
        #pragma unroll
        for (int ni = 0; ni < 4; ni++) {
            #pragma unroll
            for (int h = 0; h < 2; h++) {
                int i = m0 + rgrp + h * 8;
                if (i < W2_) {
                    int d = ni * 8 + tig * 2;
                    *(__half2*)&ctx[obase + (size_t)i * C_ + d] =
                        __floats2half2_rn(o[ni][h * 2], o[ni][h * 2 + 1]);
                }
            }
        }
    }
}

extern "C" void kernel_launch(void* const* d_in, const int* in_sizes, int n_in,
                              void* d_out, int out_size)
{
    const float* x         = (const float*)d_in[0];
    const float* g1        = (const float*)d_in[1];
    const float* b1        = (const float*)d_in[2];
    const float* wq        = (const float*)d_in[3];
    const float* bq        = (const float*)d_in[4];
    const float* wk        = (const float*)d_in[5];
    const float* bk        = (const float*)d_in[6];
    const float* wv        = (const float*)d_in[7];
    const float* bv        = (const float*)d_in[8];
    const float* rel_table = (const float*)d_in[9];
    const float* wo        = (const float*)d_in[10];
    const float* bo        = (const float*)d_in[11];
    const float* g2        = (const float*)d_in[12];
    const float* b2        = (const float*)d_in[13];
    const float* wi        = (const float*)d_in[14];
    const float* bi        = (const float*)d_in[15];
    const float* w_out     = (const float*)d_in[16];
    const float* b_out     = (const float*)d_in[17];
    const int*   rel_index = (const int*)d_in[18];
    float* out = (float*)d_out;

    __half *p_win, *p_qkv, *p_ctx, *p_h2, *p_wT;
    float  *p_x1, *p_bcat;
    cudaGetSymbolAddress((void**)&p_win,  g_win);
    cudaGetSymbolAddress((void**)&p_qkv,  g_qkv);
    cudaGetSymbolAddress((void**)&p_ctx,  g_ctx);
    cudaGetSymbolAddress((void**)&p_h2,   g_h2);
    cudaGetSymbolAddress((void**)&p_x1,   g_x1);
    cudaGetSymbolAddress((void**)&p_bcat, g_bcat);
    cudaGetSymbolAddress((void**)&p_wT,   g_wT);

    cudaFuncSetAttribute(tgemm_kernel,
                         cudaFuncAttributeMaxDynamicSharedMemorySize, SMEM_GEMM);

    // 0. weight transposes -> fp16 [N][K] K-major (qkvT = wqT|wkT|wvT stacked)
    transpose_kernel<<<dim3(16, 16), 256>>>(wq,    p_wT + WT_QKV,           C_,   C_);
    transpose_kernel<<<dim3(16, 16), 256>>>(wk,    p_wT + WT_QKV + C_*C_,   C_,   C_);
    transpose_kernel<<<dim3(16, 16), 256>>>(wv,    p_wT + WT_QKV + 2*C_*C_, C_,   C_);
    transpose_kernel<<<dim3(16, 16), 256>>>(wo,    p_wT + WT_O,             C_,   C_);
    transpose_kernel<<<dim3(64, 16), 256>>>(wi,    p_wT + WT_I,             C_,   MLPD);
    transpose_kernel<<<dim3(16, 64), 256>>>(w_out, p_wT + WT_OUT,           MLPD, C_);
    bcat_kernel<<<(C_ + 255) / 256, 256>>>(bq, bk, bv, p_bcat);

    // 1. LN1 + cyclic shift + window partition (gather) -> fp16
    ln_kernel<<<MTOK, 128>>>(x, g1, b1, p_win, 1);

    // 2. fused QKV projection -> fp16 qkv [MTOK][1536]
    dim3 gQKV(C3 / BN, MTOK / BM);
    tgemm_kernel<<<gQKV, 256, SMEM_GEMM>>>(p_win, p_wT + WT_QKV, p_bcat, p_qkv,
                                           MTOK, C3, C_, 0, nullptr, 1);

    // 3. windowed attention (tensor-core scores + softmax + PV) -> fp16 ctx
    attn_kernel<<<NWIN * HEADS_, 128>>>(p_qkv, rel_table, rel_index, p_ctx);

    // 4. output projection + window reverse + un-shift scatter + residual(x) -> fp32 x1
    dim3 gC(C_ / BN, MTOK / BM);
    tgemm_kernel<<<gC, 256, SMEM_GEMM>>>(p_ctx, p_wT + WT_O, bo, p_x1,
                                         MTOK, C_, C_, 3, x, 0);

    // 5. LN2 -> fp16
    ln_kernel<<<MTOK, 128>>>(p_x1, g2, b2, p_h2, 0);

    // 6. MLP up-projection + exact GELU -> fp16 mid (reuses qkv buffer)
    dim3 gM(MLPD / BN, MTOK / BM);
    tgemm_kernel<<<gM, 256, SMEM_GEMM>>>(p_h2, p_wT + WT_I, bi, p_qkv,
                                         MTOK, MLPD, C_, 1, nullptr, 1);

    // 7. MLP down-projection + residual(x1) -> fp32 final output
    tgemm_kernel<<<gC, 256, SMEM_GEMM>>>(p_qkv, p_wT + WT_OUT, b_out, out,
                                         MTOK, C_, MLPD, 2, p_x1, 0);
}